// round 4
// baseline (speedup 1.0000x reference)
#include <cuda_runtime.h>
#include <math.h>

// ---------------- problem constants ----------------
#define NB   2
#define DD   192
#define NHH  8
#define HDD  24
#define NPP  4
#define H0c  96
#define W0c  96
#define H1c  48
#define W1c  48
#define N0c  (H0c*W0c)      // 9216
#define N1c  (H1c*W1c)      // 2304
#define LTc  (N0c+N1c)      // 11520
#define MT   (NB*LTc)       // 23040
#define FFc  256
#define NLAY 6

// ---------------- device scratch (no allocation allowed) ----------------
__device__ float g_src [NB*LTc*DD];   // running activation, token-major
__device__ float g_pos [LTc*DD];
__device__ float g_ref [LTc*2];
__device__ float g_q   [NB*LTc*DD];
__device__ float g_off [NB*LTc*128];
__device__ float g_aw  [NB*LTc*64];
__device__ float g_v   [NB*LTc*DD];
__device__ float g_attn[NB*LTc*DD];
__device__ float g_ffn [NB*LTc*FFc];
__device__ float g_tmp [NB*LTc*DD];
__device__ float g_gnm [NB*32];
__device__ float g_gnr [NB*32];

// ---------------- pos embed + reference points ----------------
__global__ void k_pos(const float* __restrict__ level_embed) {
    int idx = blockIdx.x * blockDim.x + threadIdx.x;
    if (idx >= LTc * DD) return;
    int l = idx / DD, d = idx % DD;
    int lev, i, j, Hc, Wc;
    if (l < N0c) { lev = 0; i = l / W0c; j = l % W0c; Hc = H0c; Wc = W0c; }
    else         { lev = 1; int ll = l - N0c; i = ll / W1c; j = ll % W1c; Hc = H1c; Wc = W1c; }
    const float TWO_PI = 6.283185307179586f;
    float v; int dd;
    if (d < 96) { v = ((float)i + 0.5f) / ((float)Hc + 1e-6f) * TWO_PI; dd = d; }
    else        { v = ((float)j + 0.5f) / ((float)Wc + 1e-6f) * TWO_PI; dd = d - 96; }
    float e = (float)(2 * (dd >> 1)) / 96.0f;
    float t = v / powf(10000.0f, e);
    float val = (dd & 1) ? cosf(t) : sinf(t);
    g_pos[idx] = val + level_embed[lev * DD + d];
    if (d == 0) {
        g_ref[l * 2 + 0] = ((float)j + 0.5f) / (float)Wc;
        g_ref[l * 2 + 1] = ((float)i + 0.5f) / (float)Hc;
    }
}

// ---------------- generic SGEMM: C[M,N] = A[M,K] @ B[K,N] + bias[N] ----------------
// BM=BN=64, BK=16, 256 threads, 4x4 per thread. M%64==0, N%64==0, K%16==0 guaranteed.
template <bool RELU>
__global__ __launch_bounds__(256) void k_gemm(
    const float* __restrict__ A, const float* __restrict__ Bm,
    const float* __restrict__ bias, float* __restrict__ C,
    int Mrows, int N, int K)
{
    __shared__ float As[16][65];
    __shared__ float Bs[16][64];
    const int bm = blockIdx.y * 64, bn = blockIdx.x * 64;
    const int tid = threadIdx.x;
    const int tx = tid & 15, ty = tid >> 4;
    float acc[4][4] = {};
    for (int k0 = 0; k0 < K; k0 += 16) {
        #pragma unroll
        for (int i = 0; i < 4; i++) {
            int idx = tid + i * 256;
            int r = idx >> 4, c = idx & 15;
            As[c][r] = A[(size_t)(bm + r) * K + k0 + c];
        }
        #pragma unroll
        for (int i = 0; i < 4; i++) {
            int idx = tid + i * 256;
            int r = idx >> 6, c = idx & 63;
            Bs[r][c] = Bm[(size_t)(k0 + r) * N + bn + c];
        }
        __syncthreads();
        #pragma unroll
        for (int k = 0; k < 16; k++) {
            float a[4], b[4];
            #pragma unroll
            for (int i = 0; i < 4; i++) a[i] = As[k][ty * 4 + i];
            float4 b4 = *reinterpret_cast<const float4*>(&Bs[k][tx * 4]);
            b[0] = b4.x; b[1] = b4.y; b[2] = b4.z; b[3] = b4.w;
            #pragma unroll
            for (int i = 0; i < 4; i++)
                #pragma unroll
                for (int j = 0; j < 4; j++)
                    acc[i][j] = fmaf(a[i], b[j], acc[i][j]);
        }
        __syncthreads();
    }
    #pragma unroll
    for (int i = 0; i < 4; i++) {
        int r = bm + ty * 4 + i;
        float4 o;
        o.x = acc[i][0] + bias[bn + tx * 4 + 0];
        o.y = acc[i][1] + bias[bn + tx * 4 + 1];
        o.z = acc[i][2] + bias[bn + tx * 4 + 2];
        o.w = acc[i][3] + bias[bn + tx * 4 + 3];
        if (RELU) {
            o.x = fmaxf(o.x, 0.f); o.y = fmaxf(o.y, 0.f);
            o.z = fmaxf(o.z, 0.f); o.w = fmaxf(o.w, 0.f);
        }
        *reinterpret_cast<float4*>(&C[(size_t)r * N + bn + tx * 4]) = o;
    }
}

// ---------------- projection GEMM (both operands transposed) ----------------
// C[m,n] = sum_k A[k*M + m] * W[n*K + k] + bias[n]
// A = feat (C x HW, row-major), W = proj_w (Dout x Din, row-major).
// Output written token-major directly (ldc == N == 192).
__global__ __launch_bounds__(256) void k_gemm_tt(
    const float* __restrict__ A, const float* __restrict__ Wt,
    const float* __restrict__ bias, float* __restrict__ C,
    int Mrows, int N, int K)
{
    __shared__ float As[16][65];
    __shared__ float Bs[16][65];
    const int bm = blockIdx.y * 64, bn = blockIdx.x * 64;
    const int tid = threadIdx.x;
    const int tx = tid & 15, ty = tid >> 4;
    float acc[4][4] = {};
    for (int k0 = 0; k0 < K; k0 += 16) {
        #pragma unroll
        for (int i = 0; i < 4; i++) {
            int idx = tid + i * 256;
            int k = idx >> 6, m = idx & 63;
            As[k][m] = A[(size_t)(k0 + k) * Mrows + bm + m];
        }
        #pragma unroll
        for (int i = 0; i < 4; i++) {
            int idx = tid + i * 256;
            int n = idx >> 4, k = idx & 15;
            Bs[k][n] = Wt[(size_t)(bn + n) * K + k0 + k];
        }
        __syncthreads();
        #pragma unroll
        for (int k = 0; k < 16; k++) {
            float a[4], b[4];
            #pragma unroll
            for (int i = 0; i < 4; i++) a[i] = As[k][ty * 4 + i];
            #pragma unroll
            for (int j = 0; j < 4; j++) b[j] = Bs[k][tx * 4 + j];
            #pragma unroll
            for (int i = 0; i < 4; i++)
                #pragma unroll
                for (int j = 0; j < 4; j++)
                    acc[i][j] = fmaf(a[i], b[j], acc[i][j]);
        }
        __syncthreads();
    }
    #pragma unroll
    for (int i = 0; i < 4; i++) {
        int r = bm + ty * 4 + i;
        #pragma unroll
        for (int j = 0; j < 4; j++) {
            int cc = bn + tx * 4 + j;
            C[(size_t)r * N + cc] = acc[i][j] + bias[cc];
        }
    }
}

// ---------------- GroupNorm: stats then apply (per level) ----------------
__global__ void k_gn_stats(int tokbase, int ntok) {
    int b = blockIdx.x >> 5, g = blockIdx.x & 31;
    const float* base = g_src + (size_t)(b * LTc + tokbase) * DD + g * 6;
    float s = 0.f, ss = 0.f;
    int tot = ntok * 6;
    for (int idx = threadIdx.x; idx < tot; idx += blockDim.x) {
        int hw = idx / 6, c = idx % 6;
        float x = base[(size_t)hw * DD + c];
        s += x; ss += x * x;
    }
    #pragma unroll
    for (int o = 16; o; o >>= 1) {
        s  += __shfl_xor_sync(0xffffffffu, s, o);
        ss += __shfl_xor_sync(0xffffffffu, ss, o);
    }
    __shared__ float sh[64];
    int w = threadIdx.x >> 5, lane = threadIdx.x & 31;
    if (lane == 0) { sh[w] = s; sh[w + 32] = ss; }
    __syncthreads();
    if (threadIdx.x == 0) {
        float S = 0.f, SS = 0.f;
        for (int w2 = 0; w2 < (int)(blockDim.x >> 5); w2++) { S += sh[w2]; SS += sh[w2 + 32]; }
        float inv = 1.0f / (float)tot;
        float mu = S * inv;
        float var = SS * inv - mu * mu;
        g_gnm[b * 32 + g] = mu;
        g_gnr[b * 32 + g] = rsqrtf(var + 1e-5f);
    }
}

__global__ void k_gn_apply(int tokbase, int ntok,
                           const float* __restrict__ gg, const float* __restrict__ gb) {
    int idx = blockIdx.x * blockDim.x + threadIdx.x;
    int tot = NB * ntok * DD;
    if (idx >= tot) return;
    int c = idx % DD;
    int r = idx / DD;
    int hw = r % ntok;
    int b = r / ntok;
    size_t off = (size_t)(b * LTc + tokbase + hw) * DD + c;
    int g = c / 6;
    float x = g_src[off];
    g_src[off] = (x - g_gnm[b * 32 + g]) * g_gnr[b * 32 + g] * gg[c] + gb[c];
}

// ---------------- q = src + pos (broadcast over batch) ----------------
__global__ void k_addpos() {
    int idx = blockIdx.x * blockDim.x + threadIdx.x;
    if (idx >= NB * LTc * DD) return;
    g_q[idx] = g_src[idx] + g_pos[idx % (LTc * DD)];
}

// ---------------- softmax over 8 (per token-head) ----------------
__global__ void k_softmax8() {
    int t = blockIdx.x * blockDim.x + threadIdx.x;
    if (t >= NB * LTc * NHH) return;
    float* p = g_aw + (size_t)t * 8;
    float m = p[0];
    #pragma unroll
    for (int i = 1; i < 8; i++) m = fmaxf(m, p[i]);
    float e[8], s = 0.f;
    #pragma unroll
    for (int i = 0; i < 8; i++) { e[i] = expf(p[i] - m); s += e[i]; }
    float inv = 1.0f / s;
    #pragma unroll
    for (int i = 0; i < 8; i++) p[i] = e[i] * inv;
}

// ---------------- deformable attention gather ----------------
// One block per (b, q-token); warp h = head h; lanes 0..23 = channels.
__global__ __launch_bounds__(256) void k_deform() {
    int bq = blockIdx.x;
    int q = bq % LTc, b = bq / LTc;
    __shared__ float s_off[128];
    __shared__ float s_aw[64];
    int tid = threadIdx.x;
    size_t row = (size_t)(b * LTc + q);
    if (tid < 128)      s_off[tid]       = g_off[row * 128 + tid];
    else if (tid < 192) s_aw[tid - 128]  = g_aw[row * 64 + (tid - 128)];
    float refx = g_ref[q * 2 + 0];
    float refy = g_ref[q * 2 + 1];
    __syncthreads();
    int h = tid >> 5, lane = tid & 31;
    float acc = 0.f;
    const float* vb = g_v + (size_t)b * LTc * DD + h * HDD + lane;
    #pragma unroll
    for (int l = 0; l < 2; l++) {
        const int Wl = l ? W1c : W0c;
        const int Hl = l ? H1c : H0c;
        const int st = l ? N0c : 0;
        const float fW = (float)Wl, fH = (float)Hl;
        #pragma unroll
        for (int p = 0; p < 4; p++) {
            float ox = s_off[h * 16 + l * 8 + p * 2 + 0];
            float oy = s_off[h * 16 + l * 8 + p * 2 + 1];
            float aww = s_aw[h * 8 + l * 4 + p];
            float x = (refx + ox / fW) * fW - 0.5f;
            float y = (refy + oy / fH) * fH - 0.5f;
            float x0 = floorf(x), y0 = floorf(y);
            float wx = x - x0, wy = y - y0;
            float cw[4] = { (1.f - wx) * (1.f - wy), wx * (1.f - wy),
                            (1.f - wx) * wy,         wx * wy };
            float cx[4] = { x0, x0 + 1.f, x0, x0 + 1.f };
            float cy[4] = { y0, y0, y0 + 1.f, y0 + 1.f };
            #pragma unroll
            for (int c4 = 0; c4 < 4; c4++) {
                bool valid = (cx[c4] >= 0.f) && (cx[c4] <= fW - 1.f) &&
                             (cy[c4] >= 0.f) && (cy[c4] <= fH - 1.f);
                if (valid && lane < HDD) {
                    int xi = (int)cx[c4], yi = (int)cy[c4];
                    acc = fmaf(cw[c4] * aww, vb[(size_t)(st + yi * Wl + xi) * DD], acc);
                }
            }
        }
    }
    if (lane < HDD) g_attn[row * DD + h * HDD + lane] = acc;
}

// ---------------- fused residual + LayerNorm (warp per token, in-place on g_src) ----------------
__global__ void k_resln(const float* __restrict__ add,
                        const float* __restrict__ gw, const float* __restrict__ gb) {
    int t = (blockIdx.x * blockDim.x + threadIdx.x) >> 5;
    int lane = threadIdx.x & 31;
    if (t >= MT) return;
    size_t row = (size_t)t * DD;
    float x[6];
    float s = 0.f;
    #pragma unroll
    for (int k = 0; k < 6; k++) {
        x[k] = g_src[row + lane + 32 * k] + add[row + lane + 32 * k];
        s += x[k];
    }
    #pragma unroll
    for (int o = 16; o; o >>= 1) s += __shfl_xor_sync(0xffffffffu, s, o);
    float mu = s * (1.0f / 192.0f);
    float vs = 0.f;
    #pragma unroll
    for (int k = 0; k < 6; k++) { float d = x[k] - mu; vs += d * d; }
    #pragma unroll
    for (int o = 16; o; o >>= 1) vs += __shfl_xor_sync(0xffffffffu, vs, o);
    float rstd = rsqrtf(vs * (1.0f / 192.0f) + 1e-5f);
    #pragma unroll
    for (int k = 0; k < 6; k++) {
        int c = lane + 32 * k;
        g_src[row + c] = (x[k] - mu) * rstd * gw[c] + gb[c];
    }
}

// ---------------- output transpose: (b, tok, d) -> (b, d, tok) per level ----------------
__global__ void k_out(float* __restrict__ dst, int tokbase, int ntok) {
    __shared__ float tile[32][33];
    int b = blockIdx.z;
    int tok0 = blockIdx.x * 32, d0 = blockIdx.y * 32;
    int tx = threadIdx.x, ty = threadIdx.y;
    tile[ty][tx] = g_src[(size_t)(b * LTc + tokbase + tok0 + ty) * DD + d0 + tx];
    __syncthreads();
    dst[(size_t)b * DD * ntok + (size_t)(d0 + ty) * ntok + tok0 + tx] = tile[tx][ty];
}

// ---------------- host orchestration ----------------
extern "C" void kernel_launch(void* const* d_in, const int* in_sizes, int n_in,
                              void* d_out, int out_size) {
    const float* feat0      = (const float*)d_in[0];
    const float* feat1      = (const float*)d_in[1];
    // d_in[2] = imgs (unused)
    const float* proj_w0    = (const float*)d_in[3];
    const float* proj_b0    = (const float*)d_in[4];
    const float* gn_g0      = (const float*)d_in[5];
    const float* gn_b0      = (const float*)d_in[6];
    const float* proj_w1    = (const float*)d_in[7];
    const float* proj_b1    = (const float*)d_in[8];
    const float* gn_g1      = (const float*)d_in[9];
    const float* gn_b1      = (const float*)d_in[10];
    const float* level_emb  = (const float*)d_in[11];
    const float* so_W       = (const float*)d_in[12];
    const float* so_b       = (const float*)d_in[13];
    const float* aw_W       = (const float*)d_in[14];
    const float* aw_b       = (const float*)d_in[15];
    const float* vp_W       = (const float*)d_in[16];
    const float* vp_b       = (const float*)d_in[17];
    const float* op_W       = (const float*)d_in[18];
    const float* op_b       = (const float*)d_in[19];
    const float* ln1_g      = (const float*)d_in[20];
    const float* ln1_b      = (const float*)d_in[21];
    const float* l1_W       = (const float*)d_in[22];
    const float* l1_b       = (const float*)d_in[23];
    const float* l2_W       = (const float*)d_in[24];
    const float* l2_b       = (const float*)d_in[25];
    const float* ln2_g      = (const float*)d_in[26];
    const float* ln2_b      = (const float*)d_in[27];

    float *p_src, *p_q, *p_off, *p_aw, *p_v, *p_attn, *p_ffn, *p_tmp;
    cudaGetSymbolAddress((void**)&p_src,  g_src);
    cudaGetSymbolAddress((void**)&p_q,    g_q);
    cudaGetSymbolAddress((void**)&p_off,  g_off);
    cudaGetSymbolAddress((void**)&p_aw,   g_aw);
    cudaGetSymbolAddress((void**)&p_v,    g_v);
    cudaGetSymbolAddress((void**)&p_attn, g_attn);
    cudaGetSymbolAddress((void**)&p_ffn,  g_ffn);
    cudaGetSymbolAddress((void**)&p_tmp,  g_tmp);

    // pos embed + ref points
    k_pos<<<(LTc * DD + 255) / 256, 256>>>(level_emb);

    // projection (writes token-major directly into g_src)
    for (int b = 0; b < NB; b++) {
        k_gemm_tt<<<dim3(DD / 64, N0c / 64), 256>>>(
            feat0 + (size_t)b * DD * N0c, proj_w0, proj_b0,
            p_src + (size_t)(b * LTc) * DD, N0c, DD, DD);
        k_gemm_tt<<<dim3(DD / 64, N1c / 64), 256>>>(
            feat1 + (size_t)b * DD * N1c, proj_w1, proj_b1,
            p_src + (size_t)(b * LTc + N0c) * DD, N1c, DD, DD);
    }
    // group norm per level
    k_gn_stats<<<NB * 32, 256>>>(0, N0c);
    k_gn_apply<<<(NB * N0c * DD + 255) / 256, 256>>>(0, N0c, gn_g0, gn_b0);
    k_gn_stats<<<NB * 32, 256>>>(N0c, N1c);
    k_gn_apply<<<(NB * N1c * DD + 255) / 256, 256>>>(N0c, N1c, gn_g1, gn_b1);

    // encoder layers
    for (int i = 0; i < NLAY; i++) {
        k_addpos<<<(NB * LTc * DD + 255) / 256, 256>>>();
        k_gemm<false><<<dim3(128 / 64, MT / 64), 256>>>(
            p_q, so_W + (size_t)i * DD * 128, so_b + (size_t)i * 128, p_off, MT, 128, DD);
        k_gemm<false><<<dim3(64 / 64, MT / 64), 256>>>(
            p_q, aw_W + (size_t)i * DD * 64, aw_b + (size_t)i * 64, p_aw, MT, 64, DD);
        k_softmax8<<<(NB * LTc * NHH + 255) / 256, 256>>>();
        k_gemm<false><<<dim3(DD / 64, MT / 64), 256>>>(
            p_src, vp_W + (size_t)i * DD * DD, vp_b + (size_t)i * DD, p_v, MT, DD, DD);
        k_deform<<<NB * LTc, 256>>>();
        k_gemm<false><<<dim3(DD / 64, MT / 64), 256>>>(
            p_attn, op_W + (size_t)i * DD * DD, op_b + (size_t)i * DD, p_tmp, MT, DD, DD);
        k_resln<<<(MT * 32 + 255) / 256, 256>>>(p_tmp, ln1_g + (size_t)i * DD, ln1_b + (size_t)i * DD);
        k_gemm<true><<<dim3(FFc / 64, MT / 64), 256>>>(
            p_src, l1_W + (size_t)i * DD * FFc, l1_b + (size_t)i * FFc, p_ffn, MT, FFc, DD);
        k_gemm<false><<<dim3(DD / 64, MT / 64), 256>>>(
            p_ffn, l2_W + (size_t)i * FFc * DD, l2_b + (size_t)i * DD, p_tmp, MT, DD, FFc);
        k_resln<<<(MT * 32 + 255) / 256, 256>>>(p_tmp, ln2_g + (size_t)i * DD, ln2_b + (size_t)i * DD);
    }

    // write outputs: m0 then m1, each (B, D, H, W)
    float* out = (float*)d_out;
    k_out<<<dim3(N0c / 32, DD / 32, NB), dim3(32, 32)>>>(out, 0, N0c);
    k_out<<<dim3(N1c / 32, DD / 32, NB), dim3(32, 32)>>>(out + (size_t)NB * DD * N0c, N0c, N1c);
}

// round 5
// speedup vs baseline: 1.1259x; 1.1259x over previous
#include <cuda_runtime.h>
#include <math.h>
#include <stdint.h>

// ---------------- problem constants ----------------
#define NB   2
#define DD   192
#define NHH  8
#define HDD  24
#define NPP  4
#define H0c  96
#define W0c  96
#define H1c  48
#define W1c  48
#define N0c  (H0c*W0c)      // 9216
#define N1c  (H1c*W1c)      // 2304
#define LTc  (N0c+N1c)      // 11520
#define MT   (NB*LTc)       // 23040
#define FFc  256
#define NLAY 6

// ---------------- device scratch (no allocation allowed) ----------------
__device__ float g_src [NB*LTc*DD];   // running activation, token-major
__device__ float g_pos [LTc*DD];
__device__ float g_ref [LTc*2];
__device__ float g_q   [NB*LTc*DD];
__device__ float g_off [NB*LTc*128];
__device__ float g_aw  [NB*LTc*64];
__device__ float g_v   [NB*LTc*DD];
__device__ float g_attn[NB*LTc*DD];
__device__ float g_ffn [NB*LTc*FFc];
__device__ float g_tmp [NB*LTc*DD];
__device__ float g_gnm [NB*32];
__device__ float g_gnr [NB*32];

// ---------------- pos embed + reference points ----------------
__global__ void k_pos(const float* __restrict__ level_embed) {
    int idx = blockIdx.x * blockDim.x + threadIdx.x;
    if (idx >= LTc * DD) return;
    int l = idx / DD, d = idx % DD;
    int lev, i, j, Hc, Wc;
    if (l < N0c) { lev = 0; i = l / W0c; j = l % W0c; Hc = H0c; Wc = W0c; }
    else         { lev = 1; int ll = l - N0c; i = ll / W1c; j = ll % W1c; Hc = H1c; Wc = W1c; }
    const float TWO_PI = 6.283185307179586f;
    float v; int dd;
    if (d < 96) { v = ((float)i + 0.5f) / ((float)Hc + 1e-6f) * TWO_PI; dd = d; }
    else        { v = ((float)j + 0.5f) / ((float)Wc + 1e-6f) * TWO_PI; dd = d - 96; }
    float e = (float)(2 * (dd >> 1)) / 96.0f;
    float t = v / powf(10000.0f, e);
    float val = (dd & 1) ? cosf(t) : sinf(t);
    g_pos[idx] = val + level_embed[lev * DD + d];
    if (d == 0) {
        g_ref[l * 2 + 0] = ((float)j + 0.5f) / (float)Wc;
        g_ref[l * 2 + 1] = ((float)i + 0.5f) / (float)Hc;
    }
}

// ---------------- TF32 tensor-core GEMM (3xTF32 split for fp32 accuracy) ------
// C[M,N] = A[M,K] @ B[K,N] + bias[N], optional ReLU.
// BM=128, BN=64, BK=16, 256 threads = 8 warps (4 M x 2 N), warp tile 32x32.
// mma.sync.aligned.m16n8k8.row.col.f32.tf32.tf32.f32
__device__ __forceinline__ void split_tf32(float x, uint32_t& hi, uint32_t& lo) {
    asm("cvt.rna.tf32.f32 %0, %1;" : "=r"(hi) : "f"(x));
    float r = x - __uint_as_float(hi);
    asm("cvt.rna.tf32.f32 %0, %1;" : "=r"(lo) : "f"(r));
}

__device__ __forceinline__ void mma_tf32(float* c, const uint32_t* a, const uint32_t* b) {
    asm volatile(
        "mma.sync.aligned.m16n8k8.row.col.f32.tf32.tf32.f32 "
        "{%0,%1,%2,%3}, {%4,%5,%6,%7}, {%8,%9}, {%0,%1,%2,%3};"
        : "+f"(c[0]), "+f"(c[1]), "+f"(c[2]), "+f"(c[3])
        : "r"(a[0]), "r"(a[1]), "r"(a[2]), "r"(a[3]), "r"(b[0]), "r"(b[1]));
}

template <bool RELU>
__global__ __launch_bounds__(256) void k_gemm_tf32(
    const float* __restrict__ A, const float* __restrict__ Bm,
    const float* __restrict__ bias, float* __restrict__ C,
    int Mrows, int N, int K)
{
    __shared__ float As[2][16][132];   // [k][m], stride 132 -> conflict-free frag loads
    __shared__ float Bs[2][16][68];    // [k][n]
    const int bm = blockIdx.y * 128, bn = blockIdx.x * 64;
    const int tid = threadIdx.x;

    // A loader: 2048 elems / 256 thr = 8 each. k = tid&15, m = tid>>4 (+16*r)
    const int ak = tid & 15, am = tid >> 4;
    // B loader: 1024 elems / 256 thr = 4 each. n = tid&63, k = tid>>6 (+4*r)
    const int bn_i = tid & 63, bk_i = tid >> 6;

    const int warp = tid >> 5, lane = tid & 31;
    const int wm = (warp >> 1) * 32, wn = (warp & 1) * 32;
    const int g = lane >> 2, tig = lane & 3;

    float acc[2][4][4];
    #pragma unroll
    for (int t = 0; t < 2; t++)
        #pragma unroll
        for (int u = 0; u < 4; u++)
            #pragma unroll
            for (int r = 0; r < 4; r++) acc[t][u][r] = 0.f;

    const float* Ag = A + (size_t)bm * K;
    float ra[8], rb[4];
    #pragma unroll
    for (int r = 0; r < 8; r++) ra[r] = Ag[(size_t)(am + 16 * r) * K + ak];
    #pragma unroll
    for (int r = 0; r < 4; r++) rb[r] = Bm[(size_t)(bk_i + 4 * r) * N + bn + bn_i];
    #pragma unroll
    for (int r = 0; r < 8; r++) As[0][ak][am + 16 * r] = ra[r];
    #pragma unroll
    for (int r = 0; r < 4; r++) Bs[0][bk_i + 4 * r][bn_i] = rb[r];
    __syncthreads();

    const int niter = K / 16;
    int buf = 0;
    for (int it = 0; it < niter; it++) {
        const int k0 = (it + 1) * 16;
        const bool more = (it + 1 < niter);
        if (more) {
            #pragma unroll
            for (int r = 0; r < 8; r++) ra[r] = Ag[(size_t)(am + 16 * r) * K + k0 + ak];
            #pragma unroll
            for (int r = 0; r < 4; r++) rb[r] = Bm[(size_t)(k0 + bk_i + 4 * r) * N + bn + bn_i];
        }
        #pragma unroll
        for (int s = 0; s < 16; s += 8) {
            uint32_t ahi[2][4], alo[2][4], bhi[4][2], blo[4][2];
            #pragma unroll
            for (int t = 0; t < 2; t++) {
                float a0 = As[buf][s + tig    ][wm + t * 16 + g];
                float a1 = As[buf][s + tig    ][wm + t * 16 + g + 8];
                float a2 = As[buf][s + tig + 4][wm + t * 16 + g];
                float a3 = As[buf][s + tig + 4][wm + t * 16 + g + 8];
                split_tf32(a0, ahi[t][0], alo[t][0]);
                split_tf32(a1, ahi[t][1], alo[t][1]);
                split_tf32(a2, ahi[t][2], alo[t][2]);
                split_tf32(a3, ahi[t][3], alo[t][3]);
            }
            #pragma unroll
            for (int u = 0; u < 4; u++) {
                float b0 = Bs[buf][s + tig    ][wn + u * 8 + g];
                float b1 = Bs[buf][s + tig + 4][wn + u * 8 + g];
                split_tf32(b0, bhi[u][0], blo[u][0]);
                split_tf32(b1, bhi[u][1], blo[u][1]);
            }
            #pragma unroll
            for (int t = 0; t < 2; t++)
                #pragma unroll
                for (int u = 0; u < 4; u++) {
                    mma_tf32(acc[t][u], ahi[t], bhi[u]);
                    mma_tf32(acc[t][u], ahi[t], blo[u]);
                    mma_tf32(acc[t][u], alo[t], bhi[u]);
                }
        }
        if (more) {
            #pragma unroll
            for (int r = 0; r < 8; r++) As[buf ^ 1][ak][am + 16 * r] = ra[r];
            #pragma unroll
            for (int r = 0; r < 4; r++) Bs[buf ^ 1][bk_i + 4 * r][bn_i] = rb[r];
        }
        __syncthreads();
        buf ^= 1;
    }

    // epilogue: bias (+ optional relu), float2 stores
    #pragma unroll
    for (int t = 0; t < 2; t++) {
        int row0 = bm + wm + t * 16 + g;
        int row1 = row0 + 8;
        #pragma unroll
        for (int u = 0; u < 4; u++) {
            int col = bn + wn + u * 8 + tig * 2;
            float b0 = bias[col], b1 = bias[col + 1];
            float2 v0 = make_float2(acc[t][u][0] + b0, acc[t][u][1] + b1);
            float2 v1 = make_float2(acc[t][u][2] + b0, acc[t][u][3] + b1);
            if (RELU) {
                v0.x = fmaxf(v0.x, 0.f); v0.y = fmaxf(v0.y, 0.f);
                v1.x = fmaxf(v1.x, 0.f); v1.y = fmaxf(v1.y, 0.f);
            }
            *reinterpret_cast<float2*>(&C[(size_t)row0 * N + col]) = v0;
            *reinterpret_cast<float2*>(&C[(size_t)row1 * N + col]) = v1;
        }
    }
}

// ---------------- projection GEMM (both operands transposed, fp32) -----------
// C[m,n] = sum_k A[k*M + m] * W[n*K + k] + bias[n]
__global__ __launch_bounds__(256) void k_gemm_tt(
    const float* __restrict__ A, const float* __restrict__ Wt,
    const float* __restrict__ bias, float* __restrict__ C,
    int Mrows, int N, int K)
{
    __shared__ float As[16][65];
    __shared__ float Bs[16][65];
    const int bm = blockIdx.y * 64, bn = blockIdx.x * 64;
    const int tid = threadIdx.x;
    const int tx = tid & 15, ty = tid >> 4;
    float acc[4][4] = {};
    for (int k0 = 0; k0 < K; k0 += 16) {
        #pragma unroll
        for (int i = 0; i < 4; i++) {
            int idx = tid + i * 256;
            int k = idx >> 6, m = idx & 63;
            As[k][m] = A[(size_t)(k0 + k) * Mrows + bm + m];
        }
        #pragma unroll
        for (int i = 0; i < 4; i++) {
            int idx = tid + i * 256;
            int n = idx >> 4, k = idx & 15;
            Bs[k][n] = Wt[(size_t)(bn + n) * K + k0 + k];
        }
        __syncthreads();
        #pragma unroll
        for (int k = 0; k < 16; k++) {
            float a[4], b[4];
            #pragma unroll
            for (int i = 0; i < 4; i++) a[i] = As[k][ty * 4 + i];
            #pragma unroll
            for (int j = 0; j < 4; j++) b[j] = Bs[k][tx * 4 + j];
            #pragma unroll
            for (int i = 0; i < 4; i++)
                #pragma unroll
                for (int j = 0; j < 4; j++)
                    acc[i][j] = fmaf(a[i], b[j], acc[i][j]);
        }
        __syncthreads();
    }
    #pragma unroll
    for (int i = 0; i < 4; i++) {
        int r = bm + ty * 4 + i;
        #pragma unroll
        for (int j = 0; j < 4; j++) {
            int cc = bn + tx * 4 + j;
            C[(size_t)r * N + cc] = acc[i][j] + bias[cc];
        }
    }
}

// ---------------- GroupNorm: stats then apply (per level) ----------------
__global__ void k_gn_stats(int tokbase, int ntok) {
    int b = blockIdx.x >> 5, g = blockIdx.x & 31;
    const float* base = g_src + (size_t)(b * LTc + tokbase) * DD + g * 6;
    float s = 0.f, ss = 0.f;
    int tot = ntok * 6;
    for (int idx = threadIdx.x; idx < tot; idx += blockDim.x) {
        int hw = idx / 6, c = idx % 6;
        float x = base[(size_t)hw * DD + c];
        s += x; ss += x * x;
    }
    #pragma unroll
    for (int o = 16; o; o >>= 1) {
        s  += __shfl_xor_sync(0xffffffffu, s, o);
        ss += __shfl_xor_sync(0xffffffffu, ss, o);
    }
    __shared__ float sh[64];
    int w = threadIdx.x >> 5, lane = threadIdx.x & 31;
    if (lane == 0) { sh[w] = s; sh[w + 32] = ss; }
    __syncthreads();
    if (threadIdx.x == 0) {
        float S = 0.f, SS = 0.f;
        for (int w2 = 0; w2 < (int)(blockDim.x >> 5); w2++) { S += sh[w2]; SS += sh[w2 + 32]; }
        float inv = 1.0f / (float)tot;
        float mu = S * inv;
        float var = SS * inv - mu * mu;
        g_gnm[b * 32 + g] = mu;
        g_gnr[b * 32 + g] = rsqrtf(var + 1e-5f);
    }
}

__global__ void k_gn_apply(int tokbase, int ntok,
                           const float* __restrict__ gg, const float* __restrict__ gb) {
    int idx = blockIdx.x * blockDim.x + threadIdx.x;
    int tot = NB * ntok * DD;
    if (idx >= tot) return;
    int c = idx % DD;
    int r = idx / DD;
    int hw = r % ntok;
    int b = r / ntok;
    size_t off = (size_t)(b * LTc + tokbase + hw) * DD + c;
    int g = c / 6;
    float x = g_src[off];
    g_src[off] = (x - g_gnm[b * 32 + g]) * g_gnr[b * 32 + g] * gg[c] + gb[c];
}

// ---------------- q = src + pos (broadcast over batch) ----------------
__global__ void k_addpos() {
    int idx = blockIdx.x * blockDim.x + threadIdx.x;
    if (idx >= NB * LTc * DD) return;
    g_q[idx] = g_src[idx] + g_pos[idx % (LTc * DD)];
}

// ---------------- softmax over 8 (per token-head) ----------------
__global__ void k_softmax8() {
    int t = blockIdx.x * blockDim.x + threadIdx.x;
    if (t >= NB * LTc * NHH) return;
    float* p = g_aw + (size_t)t * 8;
    float m = p[0];
    #pragma unroll
    for (int i = 1; i < 8; i++) m = fmaxf(m, p[i]);
    float e[8], s = 0.f;
    #pragma unroll
    for (int i = 0; i < 8; i++) { e[i] = expf(p[i] - m); s += e[i]; }
    float inv = 1.0f / s;
    #pragma unroll
    for (int i = 0; i < 8; i++) p[i] = e[i] * inv;
}

// ---------------- deformable attention gather ----------------
__global__ __launch_bounds__(256) void k_deform() {
    int bq = blockIdx.x;
    int q = bq % LTc, b = bq / LTc;
    __shared__ float s_off[128];
    __shared__ float s_aw[64];
    int tid = threadIdx.x;
    size_t row = (size_t)(b * LTc + q);
    if (tid < 128)      s_off[tid]       = g_off[row * 128 + tid];
    else if (tid < 192) s_aw[tid - 128]  = g_aw[row * 64 + (tid - 128)];
    float refx = g_ref[q * 2 + 0];
    float refy = g_ref[q * 2 + 1];
    __syncthreads();
    int h = tid >> 5, lane = tid & 31;
    float acc = 0.f;
    const float* vb = g_v + (size_t)b * LTc * DD + h * HDD + lane;
    #pragma unroll
    for (int l = 0; l < 2; l++) {
        const int Wl = l ? W1c : W0c;
        const int Hl = l ? H1c : H0c;
        const int st = l ? N0c : 0;
        const float fW = (float)Wl, fH = (float)Hl;
        #pragma unroll
        for (int p = 0; p < 4; p++) {
            float ox = s_off[h * 16 + l * 8 + p * 2 + 0];
            float oy = s_off[h * 16 + l * 8 + p * 2 + 1];
            float aww = s_aw[h * 8 + l * 4 + p];
            float x = (refx + ox / fW) * fW - 0.5f;
            float y = (refy + oy / fH) * fH - 0.5f;
            float x0 = floorf(x), y0 = floorf(y);
            float wx = x - x0, wy = y - y0;
            float cw[4] = { (1.f - wx) * (1.f - wy), wx * (1.f - wy),
                            (1.f - wx) * wy,         wx * wy };
            float cx[4] = { x0, x0 + 1.f, x0, x0 + 1.f };
            float cy[4] = { y0, y0, y0 + 1.f, y0 + 1.f };
            #pragma unroll
            for (int c4 = 0; c4 < 4; c4++) {
                bool valid = (cx[c4] >= 0.f) && (cx[c4] <= fW - 1.f) &&
                             (cy[c4] >= 0.f) && (cy[c4] <= fH - 1.f);
                if (valid && lane < HDD) {
                    int xi = (int)cx[c4], yi = (int)cy[c4];
                    acc = fmaf(cw[c4] * aww, vb[(size_t)(st + yi * Wl + xi) * DD], acc);
                }
            }
        }
    }
    if (lane < HDD) g_attn[row * DD + h * HDD + lane] = acc;
}

// ---------------- fused residual + LayerNorm ----------------
__global__ void k_resln(const float* __restrict__ add,
                        const float* __restrict__ gw, const float* __restrict__ gb) {
    int t = (blockIdx.x * blockDim.x + threadIdx.x) >> 5;
    int lane = threadIdx.x & 31;
    if (t >= MT) return;
    size_t row = (size_t)t * DD;
    float x[6];
    float s = 0.f;
    #pragma unroll
    for (int k = 0; k < 6; k++) {
        x[k] = g_src[row + lane + 32 * k] + add[row + lane + 32 * k];
        s += x[k];
    }
    #pragma unroll
    for (int o = 16; o; o >>= 1) s += __shfl_xor_sync(0xffffffffu, s, o);
    float mu = s * (1.0f / 192.0f);
    float vs = 0.f;
    #pragma unroll
    for (int k = 0; k < 6; k++) { float d = x[k] - mu; vs += d * d; }
    #pragma unroll
    for (int o = 16; o; o >>= 1) vs += __shfl_xor_sync(0xffffffffu, vs, o);
    float rstd = rsqrtf(vs * (1.0f / 192.0f) + 1e-5f);
    #pragma unroll
    for (int k = 0; k < 6; k++) {
        int c = lane + 32 * k;
        g_src[row + c] = (x[k] - mu) * rstd * gw[c] + gb[c];
    }
}

// ---------------- output transpose: (b, tok, d) -> (b, d, tok) per level ------
__global__ void k_out(float* __restrict__ dst, int tokbase, int ntok) {
    __shared__ float tile[32][33];
    int b = blockIdx.z;
    int tok0 = blockIdx.x * 32, d0 = blockIdx.y * 32;
    int tx = threadIdx.x, ty = threadIdx.y;
    tile[ty][tx] = g_src[(size_t)(b * LTc + tokbase + tok0 + ty) * DD + d0 + tx];
    __syncthreads();
    dst[(size_t)b * DD * ntok + (size_t)(d0 + ty) * ntok + tok0 + tx] = tile[tx][ty];
}

// ---------------- host orchestration ----------------
extern "C" void kernel_launch(void* const* d_in, const int* in_sizes, int n_in,
                              void* d_out, int out_size) {
    const float* feat0      = (const float*)d_in[0];
    const float* feat1      = (const float*)d_in[1];
    const float* proj_w0    = (const float*)d_in[3];
    const float* proj_b0    = (const float*)d_in[4];
    const float* gn_g0      = (const float*)d_in[5];
    const float* gn_b0      = (const float*)d_in[6];
    const float* proj_w1    = (const float*)d_in[7];
    const float* proj_b1    = (const float*)d_in[8];
    const float* gn_g1      = (const float*)d_in[9];
    const float* gn_b1      = (const float*)d_in[10];
    const float* level_emb  = (const float*)d_in[11];
    const float* so_W       = (const float*)d_in[12];
    const float* so_b       = (const float*)d_in[13];
    const float* aw_W       = (const float*)d_in[14];
    const float* aw_b       = (const float*)d_in[15];
    const float* vp_W       = (const float*)d_in[16];
    const float* vp_b       = (const float*)d_in[17];
    const float* op_W       = (const float*)d_in[18];
    const float* op_b       = (const float*)d_in[19];
    const float* ln1_g      = (const float*)d_in[20];
    const float* ln1_b      = (const float*)d_in[21];
    const float* l1_W       = (const float*)d_in[22];
    const float* l1_b       = (const float*)d_in[23];
    const float* l2_W       = (const float*)d_in[24];
    const float* l2_b       = (const float*)d_in[25];
    const float* ln2_g      = (const float*)d_in[26];
    const float* ln2_b      = (const float*)d_in[27];

    float *p_src, *p_q, *p_off, *p_aw, *p_v, *p_attn, *p_ffn, *p_tmp;
    cudaGetSymbolAddress((void**)&p_src,  g_src);
    cudaGetSymbolAddress((void**)&p_q,    g_q);
    cudaGetSymbolAddress((void**)&p_off,  g_off);
    cudaGetSymbolAddress((void**)&p_aw,   g_aw);
    cudaGetSymbolAddress((void**)&p_v,    g_v);
    cudaGetSymbolAddress((void**)&p_attn, g_attn);
    cudaGetSymbolAddress((void**)&p_ffn,  g_ffn);
    cudaGetSymbolAddress((void**)&p_tmp,  g_tmp);

    // pos embed + ref points
    k_pos<<<(LTc * DD + 255) / 256, 256>>>(level_emb);

    // projection (writes token-major directly into g_src)
    for (int b = 0; b < NB; b++) {
        k_gemm_tt<<<dim3(DD / 64, N0c / 64), 256>>>(
            feat0 + (size_t)b * DD * N0c, proj_w0, proj_b0,
            p_src + (size_t)(b * LTc) * DD, N0c, DD, DD);
        k_gemm_tt<<<dim3(DD / 64, N1c / 64), 256>>>(
            feat1 + (size_t)b * DD * N1c, proj_w1, proj_b1,
            p_src + (size_t)(b * LTc + N0c) * DD, N1c, DD, DD);
    }
    // group norm per level
    k_gn_stats<<<NB * 32, 256>>>(0, N0c);
    k_gn_apply<<<(NB * N0c * DD + 255) / 256, 256>>>(0, N0c, gn_g0, gn_b0);
    k_gn_stats<<<NB * 32, 256>>>(N0c, N1c);
    k_gn_apply<<<(NB * N1c * DD + 255) / 256, 256>>>(N0c, N1c, gn_g1, gn_b1);

    // encoder layers (all big GEMMs on tensor cores via 3xTF32)
    for (int i = 0; i < NLAY; i++) {
        k_addpos<<<(NB * LTc * DD + 255) / 256, 256>>>();
        k_gemm_tf32<false><<<dim3(128 / 64, MT / 128), 256>>>(
            p_q, so_W + (size_t)i * DD * 128, so_b + (size_t)i * 128, p_off, MT, 128, DD);
        k_gemm_tf32<false><<<dim3(64 / 64, MT / 128), 256>>>(
            p_q, aw_W + (size_t)i * DD * 64, aw_b + (size_t)i * 64, p_aw, MT, 64, DD);
        k_softmax8<<<(NB * LTc * NHH + 255) / 256, 256>>>();
        k_gemm_tf32<false><<<dim3(DD / 64, MT / 128), 256>>>(
            p_src, vp_W + (size_t)i * DD * DD, vp_b + (size_t)i * DD, p_v, MT, DD, DD);
        k_deform<<<NB * LTc, 256>>>();
        k_gemm_tf32<false><<<dim3(DD / 64, MT / 128), 256>>>(
            p_attn, op_W + (size_t)i * DD * DD, op_b + (size_t)i * DD, p_tmp, MT, DD, DD);
        k_resln<<<(MT * 32 + 255) / 256, 256>>>(p_tmp, ln1_g + (size_t)i * DD, ln1_b + (size_t)i * DD);
        k_gemm_tf32<true><<<dim3(FFc / 64, MT / 128), 256>>>(
            p_src, l1_W + (size_t)i * DD * FFc, l1_b + (size_t)i * FFc, p_ffn, MT, FFc, DD);
        k_gemm_tf32<false><<<dim3(DD / 64, MT / 128), 256>>>(
            p_ffn, l2_W + (size_t)i * FFc * DD, l2_b + (size_t)i * DD, p_tmp, MT, DD, FFc);
        k_resln<<<(MT * 32 + 255) / 256, 256>>>(p_tmp, ln2_g + (size_t)i * DD, ln2_b + (size_t)i * DD);
    }

    // write outputs: m0 then m1, each (B, D, H, W)
    float* out = (float*)d_out;
    k_out<<<dim3(N0c / 32, DD / 32, NB), dim3(32, 32)>>>(out, 0, N0c);
    k_out<<<dim3(N1c / 32, DD / 32, NB), dim3(32, 32)>>>(out + (size_t)NB * DD * N0c, N0c, N1c);
}

// round 6
// speedup vs baseline: 1.3642x; 1.2117x over previous
#include <cuda_runtime.h>
#include <math.h>
#include <stdint.h>

// ---------------- problem constants ----------------
#define NB   2
#define DD   192
#define NHH  8
#define HDD  24
#define NPP  4
#define H0c  96
#define W0c  96
#define H1c  48
#define W1c  48
#define N0c  (H0c*W0c)      // 9216
#define N1c  (H1c*W1c)      // 2304
#define LTc  (N0c+N1c)      // 11520
#define MT   (NB*LTc)       // 23040
#define FFc  256
#define NLAY 6

// ---------------- device scratch (no allocation allowed) ----------------
__device__ float g_src [NB*LTc*DD];   // running activation, token-major
__device__ float g_pos [LTc*DD];
__device__ float g_ref [LTc*2];
__device__ float g_q   [NB*LTc*DD];
__device__ float g_off [NB*LTc*128];
__device__ float g_aw  [NB*LTc*64];
__device__ float g_v   [NB*LTc*DD];
__device__ float g_attn[NB*LTc*DD];
__device__ float g_ffn [NB*LTc*FFc];
__device__ float g_tmp [NB*LTc*DD];
__device__ float g_gnm [NB*32];
__device__ float g_gnr [NB*32];

// ---------------- pos embed + reference points ----------------
__global__ void k_pos(const float* __restrict__ level_embed) {
    int idx = blockIdx.x * blockDim.x + threadIdx.x;
    if (idx >= LTc * DD) return;
    int l = idx / DD, d = idx % DD;
    int lev, i, j, Hc, Wc;
    if (l < N0c) { lev = 0; i = l / W0c; j = l % W0c; Hc = H0c; Wc = W0c; }
    else         { lev = 1; int ll = l - N0c; i = ll / W1c; j = ll % W1c; Hc = H1c; Wc = W1c; }
    const float TWO_PI = 6.283185307179586f;
    float v; int dd;
    if (d < 96) { v = ((float)i + 0.5f) / ((float)Hc + 1e-6f) * TWO_PI; dd = d; }
    else        { v = ((float)j + 0.5f) / ((float)Wc + 1e-6f) * TWO_PI; dd = d - 96; }
    float e = (float)(2 * (dd >> 1)) / 96.0f;
    float t = v / powf(10000.0f, e);
    float val = (dd & 1) ? cosf(t) : sinf(t);
    g_pos[idx] = val + level_embed[lev * DD + d];
    if (d == 0) {
        g_ref[l * 2 + 0] = ((float)j + 0.5f) / (float)Wc;
        g_ref[l * 2 + 1] = ((float)i + 0.5f) / (float)Hc;
    }
}

// ---------------- TF32 tensor-core GEMM (single-pass, convert at smem fill) --
// C[M,N] = A[M,K] @ B[K,N] + bias[N], optional ReLU.
// BM=128, BN=64, BK=16, 256 threads = 8 warps (4 M x 2 N), warp tile 32x32.
__device__ __forceinline__ uint32_t f2tf32(float x) {
    uint32_t r;
    asm("cvt.rna.tf32.f32 %0, %1;" : "=r"(r) : "f"(x));
    return r;
}

__device__ __forceinline__ void mma_tf32(float* c, const uint32_t* a, const uint32_t* b) {
    asm volatile(
        "mma.sync.aligned.m16n8k8.row.col.f32.tf32.tf32.f32 "
        "{%0,%1,%2,%3}, {%4,%5,%6,%7}, {%8,%9}, {%0,%1,%2,%3};"
        : "+f"(c[0]), "+f"(c[1]), "+f"(c[2]), "+f"(c[3])
        : "r"(a[0]), "r"(a[1]), "r"(a[2]), "r"(a[3]), "r"(b[0]), "r"(b[1]));
}

template <bool RELU>
__global__ __launch_bounds__(256) void k_gemm_tf32(
    const float* __restrict__ A, const float* __restrict__ Bm,
    const float* __restrict__ bias, float* __restrict__ C,
    int Mrows, int N, int K)
{
    __shared__ uint32_t As[2][16][132];   // tf32 bits, [k][m], stride 132
    __shared__ uint32_t Bs[2][16][68];    // tf32 bits, [k][n]
    const int bm = blockIdx.y * 128, bn = blockIdx.x * 64;
    const int tid = threadIdx.x;

    // A loader: 2048 elems / 256 thr = 8 each. k = tid&15, m = tid>>4 (+16*r)
    const int ak = tid & 15, am = tid >> 4;
    // B loader: 1024 elems / 256 thr = 4 each. n = tid&63, k = tid>>6 (+4*r)
    const int bn_i = tid & 63, bk_i = tid >> 6;

    const int warp = tid >> 5, lane = tid & 31;
    const int wm = (warp >> 1) * 32, wn = (warp & 1) * 32;
    const int g = lane >> 2, tig = lane & 3;

    float acc[2][4][4];
    #pragma unroll
    for (int t = 0; t < 2; t++)
        #pragma unroll
        for (int u = 0; u < 4; u++)
            #pragma unroll
            for (int r = 0; r < 4; r++) acc[t][u][r] = 0.f;

    const float* Ag = A + (size_t)bm * K;
    float ra[8], rb[4];
    #pragma unroll
    for (int r = 0; r < 8; r++) ra[r] = Ag[(size_t)(am + 16 * r) * K + ak];
    #pragma unroll
    for (int r = 0; r < 4; r++) rb[r] = Bm[(size_t)(bk_i + 4 * r) * N + bn + bn_i];
    #pragma unroll
    for (int r = 0; r < 8; r++) As[0][ak][am + 16 * r] = f2tf32(ra[r]);
    #pragma unroll
    for (int r = 0; r < 4; r++) Bs[0][bk_i + 4 * r][bn_i] = f2tf32(rb[r]);
    __syncthreads();

    const int niter = K / 16;
    int buf = 0;
    for (int it = 0; it < niter; it++) {
        const int k0 = (it + 1) * 16;
        const bool more = (it + 1 < niter);
        if (more) {
            #pragma unroll
            for (int r = 0; r < 8; r++) ra[r] = Ag[(size_t)(am + 16 * r) * K + k0 + ak];
            #pragma unroll
            for (int r = 0; r < 4; r++) rb[r] = Bm[(size_t)(k0 + bk_i + 4 * r) * N + bn + bn_i];
        }
        #pragma unroll
        for (int s = 0; s < 16; s += 8) {
            uint32_t af[2][4], bf[4][2];
            #pragma unroll
            for (int t = 0; t < 2; t++) {
                af[t][0] = As[buf][s + tig    ][wm + t * 16 + g];
                af[t][1] = As[buf][s + tig    ][wm + t * 16 + g + 8];
                af[t][2] = As[buf][s + tig + 4][wm + t * 16 + g];
                af[t][3] = As[buf][s + tig + 4][wm + t * 16 + g + 8];
            }
            #pragma unroll
            for (int u = 0; u < 4; u++) {
                bf[u][0] = Bs[buf][s + tig    ][wn + u * 8 + g];
                bf[u][1] = Bs[buf][s + tig + 4][wn + u * 8 + g];
            }
            #pragma unroll
            for (int t = 0; t < 2; t++)
                #pragma unroll
                for (int u = 0; u < 4; u++)
                    mma_tf32(acc[t][u], af[t], bf[u]);
        }
        if (more) {
            #pragma unroll
            for (int r = 0; r < 8; r++) As[buf ^ 1][ak][am + 16 * r] = f2tf32(ra[r]);
            #pragma unroll
            for (int r = 0; r < 4; r++) Bs[buf ^ 1][bk_i + 4 * r][bn_i] = f2tf32(rb[r]);
        }
        __syncthreads();
        buf ^= 1;
    }

    // epilogue: bias (+ optional relu), float2 stores
    #pragma unroll
    for (int t = 0; t < 2; t++) {
        int row0 = bm + wm + t * 16 + g;
        int row1 = row0 + 8;
        #pragma unroll
        for (int u = 0; u < 4; u++) {
            int col = bn + wn + u * 8 + tig * 2;
            float b0 = bias[col], b1 = bias[col + 1];
            float2 v0 = make_float2(acc[t][u][0] + b0, acc[t][u][1] + b1);
            float2 v1 = make_float2(acc[t][u][2] + b0, acc[t][u][3] + b1);
            if (RELU) {
                v0.x = fmaxf(v0.x, 0.f); v0.y = fmaxf(v0.y, 0.f);
                v1.x = fmaxf(v1.x, 0.f); v1.y = fmaxf(v1.y, 0.f);
            }
            *reinterpret_cast<float2*>(&C[(size_t)row0 * N + col]) = v0;
            *reinterpret_cast<float2*>(&C[(size_t)row1 * N + col]) = v1;
        }
    }
}

// ---------------- projection GEMM (both operands transposed, fp32) -----------
// C[m,n] = sum_k A[k*M + m] * W[n*K + k] + bias[n]
__global__ __launch_bounds__(256) void k_gemm_tt(
    const float* __restrict__ A, const float* __restrict__ Wt,
    const float* __restrict__ bias, float* __restrict__ C,
    int Mrows, int N, int K)
{
    __shared__ float As[16][65];
    __shared__ float Bs[16][65];
    const int bm = blockIdx.y * 64, bn = blockIdx.x * 64;
    const int tid = threadIdx.x;
    const int tx = tid & 15, ty = tid >> 4;
    float acc[4][4] = {};
    for (int k0 = 0; k0 < K; k0 += 16) {
        #pragma unroll
        for (int i = 0; i < 4; i++) {
            int idx = tid + i * 256;
            int k = idx >> 6, m = idx & 63;
            As[k][m] = A[(size_t)(k0 + k) * Mrows + bm + m];
        }
        #pragma unroll
        for (int i = 0; i < 4; i++) {
            int idx = tid + i * 256;
            int n = idx >> 4, k = idx & 15;
            Bs[k][n] = Wt[(size_t)(bn + n) * K + k0 + k];
        }
        __syncthreads();
        #pragma unroll
        for (int k = 0; k < 16; k++) {
            float a[4], b[4];
            #pragma unroll
            for (int i = 0; i < 4; i++) a[i] = As[k][ty * 4 + i];
            #pragma unroll
            for (int j = 0; j < 4; j++) b[j] = Bs[k][tx * 4 + j];
            #pragma unroll
            for (int i = 0; i < 4; i++)
                #pragma unroll
                for (int j = 0; j < 4; j++)
                    acc[i][j] = fmaf(a[i], b[j], acc[i][j]);
        }
        __syncthreads();
    }
    #pragma unroll
    for (int i = 0; i < 4; i++) {
        int r = bm + ty * 4 + i;
        #pragma unroll
        for (int j = 0; j < 4; j++) {
            int cc = bn + tx * 4 + j;
            C[(size_t)r * N + cc] = acc[i][j] + bias[cc];
        }
    }
}

// ---------------- GroupNorm: stats then apply (per level) ----------------
__global__ void k_gn_stats(int tokbase, int ntok) {
    int b = blockIdx.x >> 5, g = blockIdx.x & 31;
    const float* base = g_src + (size_t)(b * LTc + tokbase) * DD + g * 6;
    float s = 0.f, ss = 0.f;
    int tot = ntok * 6;
    for (int idx = threadIdx.x; idx < tot; idx += blockDim.x) {
        int hw = idx / 6, c = idx % 6;
        float x = base[(size_t)hw * DD + c];
        s += x; ss += x * x;
    }
    #pragma unroll
    for (int o = 16; o; o >>= 1) {
        s  += __shfl_xor_sync(0xffffffffu, s, o);
        ss += __shfl_xor_sync(0xffffffffu, ss, o);
    }
    __shared__ float sh[64];
    int w = threadIdx.x >> 5, lane = threadIdx.x & 31;
    if (lane == 0) { sh[w] = s; sh[w + 32] = ss; }
    __syncthreads();
    if (threadIdx.x == 0) {
        float S = 0.f, SS = 0.f;
        for (int w2 = 0; w2 < (int)(blockDim.x >> 5); w2++) { S += sh[w2]; SS += sh[w2 + 32]; }
        float inv = 1.0f / (float)tot;
        float mu = S * inv;
        float var = SS * inv - mu * mu;
        g_gnm[b * 32 + g] = mu;
        g_gnr[b * 32 + g] = rsqrtf(var + 1e-5f);
    }
}

__global__ void k_gn_apply(int tokbase, int ntok,
                           const float* __restrict__ gg, const float* __restrict__ gb) {
    int idx = blockIdx.x * blockDim.x + threadIdx.x;
    int tot = NB * ntok * DD;
    if (idx >= tot) return;
    int c = idx % DD;
    int r = idx / DD;
    int hw = r % ntok;
    int b = r / ntok;
    size_t off = (size_t)(b * LTc + tokbase + hw) * DD + c;
    int g = c / 6;
    float x = g_src[off];
    g_src[off] = (x - g_gnm[b * 32 + g]) * g_gnr[b * 32 + g] * gg[c] + gb[c];
}

// ---------------- q = src + pos (broadcast over batch) ----------------
__global__ void k_addpos() {
    int idx = blockIdx.x * blockDim.x + threadIdx.x;
    if (idx >= NB * LTc * DD) return;
    g_q[idx] = g_src[idx] + g_pos[idx % (LTc * DD)];
}

// ---------------- softmax over 8 (per token-head) ----------------
__global__ void k_softmax8() {
    int t = blockIdx.x * blockDim.x + threadIdx.x;
    if (t >= NB * LTc * NHH) return;
    float* p = g_aw + (size_t)t * 8;
    float m = p[0];
    #pragma unroll
    for (int i = 1; i < 8; i++) m = fmaxf(m, p[i]);
    float e[8], s = 0.f;
    #pragma unroll
    for (int i = 0; i < 8; i++) { e[i] = expf(p[i] - m); s += e[i]; }
    float inv = 1.0f / s;
    #pragma unroll
    for (int i = 0; i < 8; i++) p[i] = e[i] * inv;
}

// ---------------- deformable attention gather ----------------
__global__ __launch_bounds__(256) void k_deform() {
    int bq = blockIdx.x;
    int q = bq % LTc, b = bq / LTc;
    __shared__ float s_off[128];
    __shared__ float s_aw[64];
    int tid = threadIdx.x;
    size_t row = (size_t)(b * LTc + q);
    if (tid < 128)      s_off[tid]       = g_off[row * 128 + tid];
    else if (tid < 192) s_aw[tid - 128]  = g_aw[row * 64 + (tid - 128)];
    float refx = g_ref[q * 2 + 0];
    float refy = g_ref[q * 2 + 1];
    __syncthreads();
    int h = tid >> 5, lane = tid & 31;
    float acc = 0.f;
    const float* vb = g_v + (size_t)b * LTc * DD + h * HDD + lane;
    #pragma unroll
    for (int l = 0; l < 2; l++) {
        const int Wl = l ? W1c : W0c;
        const int Hl = l ? H1c : H0c;
        const int st = l ? N0c : 0;
        const float fW = (float)Wl, fH = (float)Hl;
        #pragma unroll
        for (int p = 0; p < 4; p++) {
            float ox = s_off[h * 16 + l * 8 + p * 2 + 0];
            float oy = s_off[h * 16 + l * 8 + p * 2 + 1];
            float aww = s_aw[h * 8 + l * 4 + p];
            float x = (refx + ox / fW) * fW - 0.5f;
            float y = (refy + oy / fH) * fH - 0.5f;
            float x0 = floorf(x), y0 = floorf(y);
            float wx = x - x0, wy = y - y0;
            float cw[4] = { (1.f - wx) * (1.f - wy), wx * (1.f - wy),
                            (1.f - wx) * wy,         wx * wy };
            float cx[4] = { x0, x0 + 1.f, x0, x0 + 1.f };
            float cy[4] = { y0, y0, y0 + 1.f, y0 + 1.f };
            #pragma unroll
            for (int c4 = 0; c4 < 4; c4++) {
                bool valid = (cx[c4] >= 0.f) && (cx[c4] <= fW - 1.f) &&
                             (cy[c4] >= 0.f) && (cy[c4] <= fH - 1.f);
                if (valid && lane < HDD) {
                    int xi = (int)cx[c4], yi = (int)cy[c4];
                    acc = fmaf(cw[c4] * aww, vb[(size_t)(st + yi * Wl + xi) * DD], acc);
                }
            }
        }
    }
    if (lane < HDD) g_attn[row * DD + h * HDD + lane] = acc;
}

// ---------------- fused residual + LayerNorm ----------------
__global__ void k_resln(const float* __restrict__ add,
                        const float* __restrict__ gw, const float* __restrict__ gb) {
    int t = (blockIdx.x * blockDim.x + threadIdx.x) >> 5;
    int lane = threadIdx.x & 31;
    if (t >= MT) return;
    size_t row = (size_t)t * DD;
    float x[6];
    float s = 0.f;
    #pragma unroll
    for (int k = 0; k < 6; k++) {
        x[k] = g_src[row + lane + 32 * k] + add[row + lane + 32 * k];
        s += x[k];
    }
    #pragma unroll
    for (int o = 16; o; o >>= 1) s += __shfl_xor_sync(0xffffffffu, s, o);
    float mu = s * (1.0f / 192.0f);
    float vs = 0.f;
    #pragma unroll
    for (int k = 0; k < 6; k++) { float d = x[k] - mu; vs += d * d; }
    #pragma unroll
    for (int o = 16; o; o >>= 1) vs += __shfl_xor_sync(0xffffffffu, vs, o);
    float rstd = rsqrtf(vs * (1.0f / 192.0f) + 1e-5f);
    #pragma unroll
    for (int k = 0; k < 6; k++) {
        int c = lane + 32 * k;
        g_src[row + c] = (x[k] - mu) * rstd * gw[c] + gb[c];
    }
}

// ---------------- output transpose: (b, tok, d) -> (b, d, tok) per level ------
__global__ void k_out(float* __restrict__ dst, int tokbase, int ntok) {
    __shared__ float tile[32][33];
    int b = blockIdx.z;
    int tok0 = blockIdx.x * 32, d0 = blockIdx.y * 32;
    int tx = threadIdx.x, ty = threadIdx.y;
    tile[ty][tx] = g_src[(size_t)(b * LTc + tokbase + tok0 + ty) * DD + d0 + tx];
    __syncthreads();
    dst[(size_t)b * DD * ntok + (size_t)(d0 + ty) * ntok + tok0 + tx] = tile[tx][ty];
}

// ---------------- host orchestration ----------------
extern "C" void kernel_launch(void* const* d_in, const int* in_sizes, int n_in,
                              void* d_out, int out_size) {
    const float* feat0      = (const float*)d_in[0];
    const float* feat1      = (const float*)d_in[1];
    const float* proj_w0    = (const float*)d_in[3];
    const float* proj_b0    = (const float*)d_in[4];
    const float* gn_g0      = (const float*)d_in[5];
    const float* gn_b0      = (const float*)d_in[6];
    const float* proj_w1    = (const float*)d_in[7];
    const float* proj_b1    = (const float*)d_in[8];
    const float* gn_g1      = (const float*)d_in[9];
    const float* gn_b1      = (const float*)d_in[10];
    const float* level_emb  = (const float*)d_in[11];
    const float* so_W       = (const float*)d_in[12];
    const float* so_b       = (const float*)d_in[13];
    const float* aw_W       = (const float*)d_in[14];
    const float* aw_b       = (const float*)d_in[15];
    const float* vp_W       = (const float*)d_in[16];
    const float* vp_b       = (const float*)d_in[17];
    const float* op_W       = (const float*)d_in[18];
    const float* op_b       = (const float*)d_in[19];
    const float* ln1_g      = (const float*)d_in[20];
    const float* ln1_b      = (const float*)d_in[21];
    const float* l1_W       = (const float*)d_in[22];
    const float* l1_b       = (const float*)d_in[23];
    const float* l2_W       = (const float*)d_in[24];
    const float* l2_b       = (const float*)d_in[25];
    const float* ln2_g      = (const float*)d_in[26];
    const float* ln2_b      = (const float*)d_in[27];

    float *p_src, *p_q, *p_off, *p_aw, *p_v, *p_attn, *p_ffn, *p_tmp;
    cudaGetSymbolAddress((void**)&p_src,  g_src);
    cudaGetSymbolAddress((void**)&p_q,    g_q);
    cudaGetSymbolAddress((void**)&p_off,  g_off);
    cudaGetSymbolAddress((void**)&p_aw,   g_aw);
    cudaGetSymbolAddress((void**)&p_v,    g_v);
    cudaGetSymbolAddress((void**)&p_attn, g_attn);
    cudaGetSymbolAddress((void**)&p_ffn,  g_ffn);
    cudaGetSymbolAddress((void**)&p_tmp,  g_tmp);

    // pos embed + ref points
    k_pos<<<(LTc * DD + 255) / 256, 256>>>(level_emb);

    // projection (writes token-major directly into g_src)
    for (int b = 0; b < NB; b++) {
        k_gemm_tt<<<dim3(DD / 64, N0c / 64), 256>>>(
            feat0 + (size_t)b * DD * N0c, proj_w0, proj_b0,
            p_src + (size_t)(b * LTc) * DD, N0c, DD, DD);
        k_gemm_tt<<<dim3(DD / 64, N1c / 64), 256>>>(
            feat1 + (size_t)b * DD * N1c, proj_w1, proj_b1,
            p_src + (size_t)(b * LTc + N0c) * DD, N1c, DD, DD);
    }
    // group norm per level
    k_gn_stats<<<NB * 32, 256>>>(0, N0c);
    k_gn_apply<<<(NB * N0c * DD + 255) / 256, 256>>>(0, N0c, gn_g0, gn_b0);
    k_gn_stats<<<NB * 32, 256>>>(N0c, N1c);
    k_gn_apply<<<(NB * N1c * DD + 255) / 256, 256>>>(N0c, N1c, gn_g1, gn_b1);

    // encoder layers (all big GEMMs on tensor cores, single-pass TF32)
    for (int i = 0; i < NLAY; i++) {
        k_addpos<<<(NB * LTc * DD + 255) / 256, 256>>>();
        k_gemm_tf32<false><<<dim3(128 / 64, MT / 128), 256>>>(
            p_q, so_W + (size_t)i * DD * 128, so_b + (size_t)i * 128, p_off, MT, 128, DD);
        k_gemm_tf32<false><<<dim3(64 / 64, MT / 128), 256>>>(
            p_q, aw_W + (size_t)i * DD * 64, aw_b + (size_t)i * 64, p_aw, MT, 64, DD);
        k_softmax8<<<(NB * LTc * NHH + 255) / 256, 256>>>();
        k_gemm_tf32<false><<<dim3(DD / 64, MT / 128), 256>>>(
            p_src, vp_W + (size_t)i * DD * DD, vp_b + (size_t)i * DD, p_v, MT, DD, DD);
        k_deform<<<NB * LTc, 256>>>();
        k_gemm_tf32<false><<<dim3(DD / 64, MT / 128), 256>>>(
            p_attn, op_W + (size_t)i * DD * DD, op_b + (size_t)i * DD, p_tmp, MT, DD, DD);
        k_resln<<<(MT * 32 + 255) / 256, 256>>>(p_tmp, ln1_g + (size_t)i * DD, ln1_b + (size_t)i * DD);
        k_gemm_tf32<true><<<dim3(FFc / 64, MT / 128), 256>>>(
            p_src, l1_W + (size_t)i * DD * FFc, l1_b + (size_t)i * FFc, p_ffn, MT, FFc, DD);
        k_gemm_tf32<false><<<dim3(DD / 64, MT / 128), 256>>>(
            p_ffn, l2_W + (size_t)i * FFc * DD, l2_b + (size_t)i * DD, p_tmp, MT, DD, FFc);
        k_resln<<<(MT * 32 + 255) / 256, 256>>>(p_tmp, ln2_g + (size_t)i * DD, ln2_b + (size_t)i * DD);
    }

    // write outputs: m0 then m1, each (B, D, H, W)
    float* out = (float*)d_out;
    k_out<<<dim3(N0c / 32, DD / 32, NB), dim3(32, 32)>>>(out, 0, N0c);
    k_out<<<dim3(N1c / 32, DD / 32, NB), dim3(32, 32)>>>(out + (size_t)NB * DD * N0c, N0c, N1c);
}

// round 7
// speedup vs baseline: 1.4269x; 1.0459x over previous
#include <cuda_runtime.h>
#include <math.h>
#include <stdint.h>

// ---------------- problem constants ----------------
#define NB   2
#define DD   192
#define NHH  8
#define HDD  24
#define H0c  96
#define W0c  96
#define H1c  48
#define W1c  48
#define N0c  (H0c*W0c)      // 9216
#define N1c  (H1c*W1c)      // 2304
#define LTc  (N0c+N1c)      // 11520
#define MT   (NB*LTc)       // 23040
#define FFc  256
#define NLAY 6

// ---------------- device scratch ----------------
__device__ float g_src  [MT*DD];      // running activation, token-major
__device__ float g_pos  [LTc*DD];
__device__ float g_ref  [LTc*2];
__device__ float g_offaw[MT*DD];      // combined offsets(128) + aw logits(64)
__device__ float g_v    [MT*DD];
__device__ float g_attn [MT*DD];
__device__ float g_ffn  [MT*FFc];
__device__ float g_wcomb[NLAY*DD*DD]; // so_W || aw_W packed per layer
__device__ float g_bcomb[NLAY*DD];
__device__ float g_gnm  [NB*32];
__device__ float g_gnr  [NB*32];

// ---------------- helpers ----------------
__device__ __forceinline__ uint32_t f2tf32(float x) {
    uint32_t r;
    asm("cvt.rna.tf32.f32 %0, %1;" : "=r"(r) : "f"(x));
    return r;
}
__device__ __forceinline__ void mma_tf32(float* c, const uint32_t* a, const uint32_t* b) {
    asm volatile(
        "mma.sync.aligned.m16n8k8.row.col.f32.tf32.tf32.f32 "
        "{%0,%1,%2,%3}, {%4,%5,%6,%7}, {%8,%9}, {%0,%1,%2,%3};"
        : "+f"(c[0]), "+f"(c[1]), "+f"(c[2]), "+f"(c[3])
        : "r"(a[0]), "r"(a[1]), "r"(a[2]), "r"(a[3]), "r"(b[0]), "r"(b[1]));
}

// ---------------- pos embed + reference points ----------------
__global__ void k_pos(const float* __restrict__ level_embed) {
    int idx = blockIdx.x * blockDim.x + threadIdx.x;
    if (idx >= LTc * DD) return;
    int l = idx / DD, d = idx % DD;
    int lev, i, j, Hc, Wc;
    if (l < N0c) { lev = 0; i = l / W0c; j = l % W0c; Hc = H0c; Wc = W0c; }
    else         { lev = 1; int ll = l - N0c; i = ll / W1c; j = ll % W1c; Hc = H1c; Wc = W1c; }
    const float TWO_PI = 6.283185307179586f;
    float v; int dd;
    if (d < 96) { v = ((float)i + 0.5f) / ((float)Hc + 1e-6f) * TWO_PI; dd = d; }
    else        { v = ((float)j + 0.5f) / ((float)Wc + 1e-6f) * TWO_PI; dd = d - 96; }
    float e = (float)(2 * (dd >> 1)) / 96.0f;
    float t = v / powf(10000.0f, e);
    float val = (dd & 1) ? cosf(t) : sinf(t);
    g_pos[idx] = val + level_embed[lev * DD + d];
    if (d == 0) {
        g_ref[l * 2 + 0] = ((float)j + 0.5f) / (float)Wc;
        g_ref[l * 2 + 1] = ((float)i + 0.5f) / (float)Hc;
    }
}

// ---------------- pack so_W||aw_W into one [D,192] weight per layer ----------
__global__ void k_pack(const float* __restrict__ soW, const float* __restrict__ sob,
                       const float* __restrict__ awW, const float* __restrict__ awb) {
    int idx = blockIdx.x * blockDim.x + threadIdx.x;
    if (idx < NLAY * DD * DD) {
        int i = idx / (DD * DD);
        int rem = idx % (DD * DD);
        int k = rem / DD, n = rem % DD;
        g_wcomb[idx] = (n < 128) ? soW[(size_t)i * DD * 128 + k * 128 + n]
                                 : awW[(size_t)i * DD * 64 + k * 64 + (n - 128)];
    }
    if (idx < NLAY * DD) {
        int i = idx / DD, n = idx % DD;
        g_bcomb[idx] = (n < 128) ? sob[i * 128 + n] : awb[i * 64 + (n - 128)];
    }
}

// ---------------- TF32 GEMM: C[M,N] = A[M,K] @ B[K,N] + bias ----------------
// BM=128, BN=64, BK=16, 256 thr, 8 warps (4m x 2n), warp tile 32x32.
// ADDPOS: A_eff[m,k] = A[m,k] + pos[(m mod LTc), k]   (requires K == DD)
template <bool RELU, bool ADDPOS>
__global__ __launch_bounds__(256) void k_gemm_tf32(
    const float* __restrict__ A, const float* __restrict__ Bm,
    const float* __restrict__ bias, float* __restrict__ C,
    int N, int K)
{
    __shared__ uint32_t As[2][16][132];
    __shared__ uint32_t Bs[2][16][68];
    const int bm = blockIdx.y * 128, bn = blockIdx.x * 64;
    const int tid = threadIdx.x;
    const int ak = tid & 15, am = tid >> 4;
    const int bn_i = tid & 63, bk_i = tid >> 6;
    const int warp = tid >> 5, lane = tid & 31;
    const int wm = (warp >> 1) * 32, wn = (warp & 1) * 32;
    const int g = lane >> 2, tig = lane & 3;

    float acc[2][4][4];
    #pragma unroll
    for (int t = 0; t < 2; t++)
        #pragma unroll
        for (int u = 0; u < 4; u++)
            #pragma unroll
            for (int r = 0; r < 4; r++) acc[t][u][r] = 0.f;

    const float* Ag = A + (size_t)bm * K;
    float ra[8], rb[4];
    #pragma unroll
    for (int r = 0; r < 8; r++) {
        float v = Ag[(size_t)(am + 16 * r) * K + ak];
        if (ADDPOS) {
            int rowg = bm + am + 16 * r;
            int posr = rowg >= LTc ? rowg - LTc : rowg;
            v += g_pos[(size_t)posr * DD + ak];
        }
        ra[r] = v;
    }
    #pragma unroll
    for (int r = 0; r < 4; r++) rb[r] = Bm[(size_t)(bk_i + 4 * r) * N + bn + bn_i];
    #pragma unroll
    for (int r = 0; r < 8; r++) As[0][ak][am + 16 * r] = f2tf32(ra[r]);
    #pragma unroll
    for (int r = 0; r < 4; r++) Bs[0][bk_i + 4 * r][bn_i] = f2tf32(rb[r]);
    __syncthreads();

    const int niter = K / 16;
    int buf = 0;
    for (int it = 0; it < niter; it++) {
        const int k0 = (it + 1) * 16;
        const bool more = (it + 1 < niter);
        if (more) {
            #pragma unroll
            for (int r = 0; r < 8; r++) {
                float v = Ag[(size_t)(am + 16 * r) * K + k0 + ak];
                if (ADDPOS) {
                    int rowg = bm + am + 16 * r;
                    int posr = rowg >= LTc ? rowg - LTc : rowg;
                    v += g_pos[(size_t)posr * DD + k0 + ak];
                }
                ra[r] = v;
            }
            #pragma unroll
            for (int r = 0; r < 4; r++) rb[r] = Bm[(size_t)(k0 + bk_i + 4 * r) * N + bn + bn_i];
        }
        #pragma unroll
        for (int s = 0; s < 16; s += 8) {
            uint32_t af[2][4], bf[4][2];
            #pragma unroll
            for (int t = 0; t < 2; t++) {
                af[t][0] = As[buf][s + tig    ][wm + t * 16 + g];
                af[t][1] = As[buf][s + tig    ][wm + t * 16 + g + 8];
                af[t][2] = As[buf][s + tig + 4][wm + t * 16 + g];
                af[t][3] = As[buf][s + tig + 4][wm + t * 16 + g + 8];
            }
            #pragma unroll
            for (int u = 0; u < 4; u++) {
                bf[u][0] = Bs[buf][s + tig    ][wn + u * 8 + g];
                bf[u][1] = Bs[buf][s + tig + 4][wn + u * 8 + g];
            }
            #pragma unroll
            for (int t = 0; t < 2; t++)
                #pragma unroll
                for (int u = 0; u < 4; u++)
                    mma_tf32(acc[t][u], af[t], bf[u]);
        }
        if (more) {
            #pragma unroll
            for (int r = 0; r < 8; r++) As[buf ^ 1][ak][am + 16 * r] = f2tf32(ra[r]);
            #pragma unroll
            for (int r = 0; r < 4; r++) Bs[buf ^ 1][bk_i + 4 * r][bn_i] = f2tf32(rb[r]);
        }
        __syncthreads();
        buf ^= 1;
    }

    #pragma unroll
    for (int t = 0; t < 2; t++) {
        int row0 = bm + wm + t * 16 + g;
        int row1 = row0 + 8;
        #pragma unroll
        for (int u = 0; u < 4; u++) {
            int col = bn + wn + u * 8 + tig * 2;
            float b0 = bias[col], b1 = bias[col + 1];
            float2 v0 = make_float2(acc[t][u][0] + b0, acc[t][u][1] + b1);
            float2 v1 = make_float2(acc[t][u][2] + b0, acc[t][u][3] + b1);
            if (RELU) {
                v0.x = fmaxf(v0.x, 0.f); v0.y = fmaxf(v0.y, 0.f);
                v1.x = fmaxf(v1.x, 0.f); v1.y = fmaxf(v1.y, 0.f);
            }
            *reinterpret_cast<float2*>(&C[(size_t)row0 * N + col]) = v0;
            *reinterpret_cast<float2*>(&C[(size_t)row1 * N + col]) = v1;
        }
    }
}

// ---------------- TF32 GEMM + fused residual + LayerNorm --------------------
// C_row = LN(res_row + A@W + bias) * gamma + beta, written to res (g_src).
// BM=128, BN=192 (full row), BK=16, 256 thr, 8 warps (4m x 2n), warp 32x96.
__global__ __launch_bounds__(256) void k_gemm_ln(
    const float* __restrict__ A, const float* __restrict__ Bm,
    const float* __restrict__ bias,
    const float* __restrict__ gamma, const float* __restrict__ beta,
    float* __restrict__ res,   // residual input AND output (g_src)
    int K)
{
    __shared__ __align__(16) char sbuf[16896 + 25600];
    uint32_t (*As)[16][132] = reinterpret_cast<uint32_t(*)[16][132]>(sbuf);
    uint32_t (*Bs)[16][200] = reinterpret_cast<uint32_t(*)[16][200]>(sbuf + 16896);

    const int bm = blockIdx.x * 128;
    const int tid = threadIdx.x;
    const int ak = tid & 15, am = tid >> 4;
    const int bk = tid >> 4, bn0 = tid & 15;      // B: one k-row, 12 n values
    const int warp = tid >> 5, lane = tid & 31;
    const int wm = (warp >> 1) * 32, wn = (warp & 1) * 96;
    const int g = lane >> 2, tig = lane & 3;

    float acc[2][12][4];
    #pragma unroll
    for (int t = 0; t < 2; t++)
        #pragma unroll
        for (int u = 0; u < 12; u++)
            #pragma unroll
            for (int r = 0; r < 4; r++) acc[t][u][r] = 0.f;

    const float* Ag = A + (size_t)bm * K;
    float ra[8], rb[12];
    #pragma unroll
    for (int r = 0; r < 8; r++) ra[r] = Ag[(size_t)(am + 16 * r) * K + ak];
    #pragma unroll
    for (int r = 0; r < 12; r++) rb[r] = Bm[(size_t)bk * DD + bn0 + 16 * r];
    #pragma unroll
    for (int r = 0; r < 8; r++) As[0][ak][am + 16 * r] = f2tf32(ra[r]);
    #pragma unroll
    for (int r = 0; r < 12; r++) Bs[0][bk][bn0 + 16 * r] = f2tf32(rb[r]);
    __syncthreads();

    const int niter = K / 16;
    int buf = 0;
    for (int it = 0; it < niter; it++) {
        const int k0 = (it + 1) * 16;
        const bool more = (it + 1 < niter);
        if (more) {
            #pragma unroll
            for (int r = 0; r < 8; r++) ra[r] = Ag[(size_t)(am + 16 * r) * K + k0 + ak];
            #pragma unroll
            for (int r = 0; r < 12; r++) rb[r] = Bm[(size_t)(k0 + bk) * DD + bn0 + 16 * r];
        }
        #pragma unroll
        for (int s = 0; s < 16; s += 8) {
            uint32_t af[2][4], bf[12][2];
            #pragma unroll
            for (int t = 0; t < 2; t++) {
                af[t][0] = As[buf][s + tig    ][wm + t * 16 + g];
                af[t][1] = As[buf][s + tig    ][wm + t * 16 + g + 8];
                af[t][2] = As[buf][s + tig + 4][wm + t * 16 + g];
                af[t][3] = As[buf][s + tig + 4][wm + t * 16 + g + 8];
            }
            #pragma unroll
            for (int u = 0; u < 12; u++) {
                bf[u][0] = Bs[buf][s + tig    ][wn + u * 8 + g];
                bf[u][1] = Bs[buf][s + tig + 4][wn + u * 8 + g];
            }
            #pragma unroll
            for (int t = 0; t < 2; t++)
                #pragma unroll
                for (int u = 0; u < 12; u++)
                    mma_tf32(acc[t][u], af[t], bf[u]);
        }
        if (more) {
            #pragma unroll
            for (int r = 0; r < 8; r++) As[buf ^ 1][ak][am + 16 * r] = f2tf32(ra[r]);
            #pragma unroll
            for (int r = 0; r < 12; r++) Bs[buf ^ 1][bk][bn0 + 16 * r] = f2tf32(rb[r]);
        }
        __syncthreads();
        buf ^= 1;
    }

    // ---- fused epilogue: x = acc + bias + res; LayerNorm per row ----
    float* psum  = reinterpret_cast<float*>(sbuf);          // [128][8]
    float* psum2 = psum + 128 * 8;                          // [128][8]
    float* smu   = psum2 + 128 * 8;                         // [128]
    float* srstd = smu + 128;                               // [128]
    const int widx = (warp & 1) * 4 + tig;

    #pragma unroll
    for (int t = 0; t < 2; t++) {
        #pragma unroll
        for (int half = 0; half < 2; half++) {
            int row = wm + t * 16 + g + half * 8;
            const float* rr = res + (size_t)(bm + row) * DD;
            float s = 0.f, s2 = 0.f;
            #pragma unroll
            for (int u = 0; u < 12; u++) {
                int col = wn + u * 8 + tig * 2;
                float2 rv = *reinterpret_cast<const float2*>(&rr[col]);
                float x0 = acc[t][u][half * 2 + 0] + bias[col]     + rv.x;
                float x1 = acc[t][u][half * 2 + 1] + bias[col + 1] + rv.y;
                acc[t][u][half * 2 + 0] = x0;
                acc[t][u][half * 2 + 1] = x1;
                s += x0 + x1;
                s2 += x0 * x0 + x1 * x1;
            }
            psum [row * 8 + widx] = s;
            psum2[row * 8 + widx] = s2;
        }
    }
    __syncthreads();
    if (tid < 128) {
        float s = 0.f, s2 = 0.f;
        #pragma unroll
        for (int j = 0; j < 8; j++) { s += psum[tid * 8 + j]; s2 += psum2[tid * 8 + j]; }
        float mu = s * (1.0f / 192.0f);
        float var = s2 * (1.0f / 192.0f) - mu * mu;
        smu[tid] = mu;
        srstd[tid] = rsqrtf(var + 1e-5f);
    }
    __syncthreads();
    #pragma unroll
    for (int t = 0; t < 2; t++) {
        #pragma unroll
        for (int half = 0; half < 2; half++) {
            int row = wm + t * 16 + g + half * 8;
            float mu = smu[row], rs = srstd[row];
            float* wr = res + (size_t)(bm + row) * DD;
            #pragma unroll
            for (int u = 0; u < 12; u++) {
                int col = wn + u * 8 + tig * 2;
                float2 o;
                o.x = (acc[t][u][half * 2 + 0] - mu) * rs * gamma[col]     + beta[col];
                o.y = (acc[t][u][half * 2 + 1] - mu) * rs * gamma[col + 1] + beta[col + 1];
                *reinterpret_cast<float2*>(&wr[col]) = o;
            }
        }
    }
}

// ---------------- projection GEMM (transposed operands), TF32 ---------------
// C[m,n] = sum_k A[k*M + m] * W[n*K + k] + bias[n]; C stride DD (token-major)
__global__ __launch_bounds__(256) void k_proj_tf32(
    const float* __restrict__ A, const float* __restrict__ Wt,
    const float* __restrict__ bias, float* __restrict__ C,
    int Mstride)
{
    __shared__ uint32_t As[2][16][132];
    __shared__ uint32_t Bs[2][16][68];
    const int bm = blockIdx.y * 128, bn = blockIdx.x * 64;
    const int tid = threadIdx.x;
    const int am = tid & 127, ak0 = tid >> 7;      // A: m fastest, k = ak0 + 2r
    const int bk = tid & 15, bn0 = tid >> 4;       // B: k fastest, n = bn0 + 16r
    const int warp = tid >> 5, lane = tid & 31;
    const int wm = (warp >> 1) * 32, wn = (warp & 1) * 32;
    const int g = lane >> 2, tig = lane & 3;
    const int K = DD;

    float acc[2][4][4];
    #pragma unroll
    for (int t = 0; t < 2; t++)
        #pragma unroll
        for (int u = 0; u < 4; u++)
            #pragma unroll
            for (int r = 0; r < 4; r++) acc[t][u][r] = 0.f;

    float ra[8], rb[4];
    #pragma unroll
    for (int r = 0; r < 8; r++) ra[r] = A[(size_t)(ak0 + 2 * r) * Mstride + bm + am];
    #pragma unroll
    for (int r = 0; r < 4; r++) rb[r] = Wt[(size_t)(bn + bn0 + 16 * r) * K + bk];
    #pragma unroll
    for (int r = 0; r < 8; r++) As[0][ak0 + 2 * r][am] = f2tf32(ra[r]);
    #pragma unroll
    for (int r = 0; r < 4; r++) Bs[0][bk][bn0 + 16 * r] = f2tf32(rb[r]);
    __syncthreads();

    const int niter = K / 16;
    int buf = 0;
    for (int it = 0; it < niter; it++) {
        const int k0 = (it + 1) * 16;
        const bool more = (it + 1 < niter);
        if (more) {
            #pragma unroll
            for (int r = 0; r < 8; r++) ra[r] = A[(size_t)(k0 + ak0 + 2 * r) * Mstride + bm + am];
            #pragma unroll
            for (int r = 0; r < 4; r++) rb[r] = Wt[(size_t)(bn + bn0 + 16 * r) * K + k0 + bk];
        }
        #pragma unroll
        for (int s = 0; s < 16; s += 8) {
            uint32_t af[2][4], bf[4][2];
            #pragma unroll
            for (int t = 0; t < 2; t++) {
                af[t][0] = As[buf][s + tig    ][wm + t * 16 + g];
                af[t][1] = As[buf][s + tig    ][wm + t * 16 + g + 8];
                af[t][2] = As[buf][s + tig + 4][wm + t * 16 + g];
                af[t][3] = As[buf][s + tig + 4][wm + t * 16 + g + 8];
            }
            #pragma unroll
            for (int u = 0; u < 4; u++) {
                bf[u][0] = Bs[buf][s + tig    ][wn + u * 8 + g];
                bf[u][1] = Bs[buf][s + tig + 4][wn + u * 8 + g];
            }
            #pragma unroll
            for (int t = 0; t < 2; t++)
                #pragma unroll
                for (int u = 0; u < 4; u++)
                    mma_tf32(acc[t][u], af[t], bf[u]);
        }
        if (more) {
            #pragma unroll
            for (int r = 0; r < 8; r++) As[buf ^ 1][ak0 + 2 * r][am] = f2tf32(ra[r]);
            #pragma unroll
            for (int r = 0; r < 4; r++) Bs[buf ^ 1][bk][bn0 + 16 * r] = f2tf32(rb[r]);
        }
        __syncthreads();
        buf ^= 1;
    }

    #pragma unroll
    for (int t = 0; t < 2; t++) {
        int row0 = bm + wm + t * 16 + g;
        int row1 = row0 + 8;
        #pragma unroll
        for (int u = 0; u < 4; u++) {
            int col = bn + wn + u * 8 + tig * 2;
            float b0 = bias[col], b1 = bias[col + 1];
            float2 v0 = make_float2(acc[t][u][0] + b0, acc[t][u][1] + b1);
            float2 v1 = make_float2(acc[t][u][2] + b0, acc[t][u][3] + b1);
            *reinterpret_cast<float2*>(&C[(size_t)row0 * DD + col]) = v0;
            *reinterpret_cast<float2*>(&C[(size_t)row1 * DD + col]) = v1;
        }
    }
}

// ---------------- GroupNorm: stats then apply (per level) ----------------
__global__ void k_gn_stats(int tokbase, int ntok) {
    int b = blockIdx.x >> 5, g = blockIdx.x & 31;
    const float* base = g_src + (size_t)(b * LTc + tokbase) * DD + g * 6;
    float s = 0.f, ss = 0.f;
    int tot = ntok * 6;
    for (int idx = threadIdx.x; idx < tot; idx += blockDim.x) {
        int hw = idx / 6, c = idx % 6;
        float x = base[(size_t)hw * DD + c];
        s += x; ss += x * x;
    }
    #pragma unroll
    for (int o = 16; o; o >>= 1) {
        s  += __shfl_xor_sync(0xffffffffu, s, o);
        ss += __shfl_xor_sync(0xffffffffu, ss, o);
    }
    __shared__ float sh[64];
    int w = threadIdx.x >> 5, lane = threadIdx.x & 31;
    if (lane == 0) { sh[w] = s; sh[w + 32] = ss; }
    __syncthreads();
    if (threadIdx.x == 0) {
        float S = 0.f, SS = 0.f;
        for (int w2 = 0; w2 < (int)(blockDim.x >> 5); w2++) { S += sh[w2]; SS += sh[w2 + 32]; }
        float inv = 1.0f / (float)tot;
        float mu = S * inv;
        float var = SS * inv - mu * mu;
        g_gnm[b * 32 + g] = mu;
        g_gnr[b * 32 + g] = rsqrtf(var + 1e-5f);
    }
}

__global__ void k_gn_apply(int tokbase, int ntok,
                           const float* __restrict__ gg, const float* __restrict__ gb) {
    int idx = blockIdx.x * blockDim.x + threadIdx.x;
    int tot = NB * ntok * DD;
    if (idx >= tot) return;
    int c = idx % DD;
    int r = idx / DD;
    int hw = r % ntok;
    int b = r / ntok;
    size_t off = (size_t)(b * LTc + tokbase + hw) * DD + c;
    int g = c / 6;
    float x = g_src[off];
    g_src[off] = (x - g_gnm[b * 32 + g]) * g_gnr[b * 32 + g] * gg[c] + gb[c];
}

// ---------------- deformable attention gather (softmax fused) ----------------
__global__ __launch_bounds__(256) void k_deform() {
    int bq = blockIdx.x;
    int q = bq % LTc, b = bq / LTc;
    __shared__ float s_off[128];
    __shared__ float s_aw[64];
    int tid = threadIdx.x;
    size_t row = (size_t)(b * LTc + q);
    if (tid < 192) {
        float v = g_offaw[row * DD + tid];
        if (tid < 128) s_off[tid] = v;
        else           s_aw[tid - 128] = v;
    }
    float refx = g_ref[q * 2 + 0];
    float refy = g_ref[q * 2 + 1];
    __syncthreads();
    int h = tid >> 5, lane = tid & 31;

    // softmax over this head's 8 logits (redundant per lane; registers)
    float wv[8];
    float m = -1e30f;
    #pragma unroll
    for (int i = 0; i < 8; i++) { wv[i] = s_aw[h * 8 + i]; m = fmaxf(m, wv[i]); }
    float sum = 0.f;
    #pragma unroll
    for (int i = 0; i < 8; i++) { wv[i] = expf(wv[i] - m); sum += wv[i]; }
    float inv = 1.0f / sum;
    #pragma unroll
    for (int i = 0; i < 8; i++) wv[i] *= inv;

    float acc = 0.f;
    const float* vb = g_v + (size_t)b * LTc * DD + h * HDD + lane;
    #pragma unroll
    for (int l = 0; l < 2; l++) {
        const int Wl = l ? W1c : W0c;
        const int Hl = l ? H1c : H0c;
        const int st = l ? N0c : 0;
        const float fW = (float)Wl, fH = (float)Hl;
        #pragma unroll
        for (int p = 0; p < 4; p++) {
            float ox = s_off[h * 16 + l * 8 + p * 2 + 0];
            float oy = s_off[h * 16 + l * 8 + p * 2 + 1];
            float aww = wv[l * 4 + p];
            float x = (refx + ox / fW) * fW - 0.5f;
            float y = (refy + oy / fH) * fH - 0.5f;
            float x0 = floorf(x), y0 = floorf(y);
            float wx = x - x0, wy = y - y0;
            float cw[4] = { (1.f - wx) * (1.f - wy), wx * (1.f - wy),
                            (1.f - wx) * wy,         wx * wy };
            float cx[4] = { x0, x0 + 1.f, x0, x0 + 1.f };
            float cy[4] = { y0, y0, y0 + 1.f, y0 + 1.f };
            #pragma unroll
            for (int c4 = 0; c4 < 4; c4++) {
                bool valid = (cx[c4] >= 0.f) && (cx[c4] <= fW - 1.f) &&
                             (cy[c4] >= 0.f) && (cy[c4] <= fH - 1.f);
                if (valid && lane < HDD) {
                    int xi = (int)cx[c4], yi = (int)cy[c4];
                    acc = fmaf(cw[c4] * aww, vb[(size_t)(st + yi * Wl + xi) * DD], acc);
                }
            }
        }
    }
    if (lane < HDD) g_attn[row * DD + h * HDD + lane] = acc;
}

// ---------------- output transpose: (b, tok, d) -> (b, d, tok) per level ------
__global__ void k_out(float* __restrict__ dst, int tokbase, int ntok) {
    __shared__ float tile[32][33];
    int b = blockIdx.z;
    int tok0 = blockIdx.x * 32, d0 = blockIdx.y * 32;
    int tx = threadIdx.x, ty = threadIdx.y;
    tile[ty][tx] = g_src[(size_t)(b * LTc + tokbase + tok0 + ty) * DD + d0 + tx];
    __syncthreads();
    dst[(size_t)b * DD * ntok + (size_t)(d0 + ty) * ntok + tok0 + tx] = tile[tx][ty];
}

// ---------------- host orchestration ----------------
extern "C" void kernel_launch(void* const* d_in, const int* in_sizes, int n_in,
                              void* d_out, int out_size) {
    const float* feat0      = (const float*)d_in[0];
    const float* feat1      = (const float*)d_in[1];
    const float* proj_w0    = (const float*)d_in[3];
    const float* proj_b0    = (const float*)d_in[4];
    const float* gn_g0      = (const float*)d_in[5];
    const float* gn_b0      = (const float*)d_in[6];
    const float* proj_w1    = (const float*)d_in[7];
    const float* proj_b1    = (const float*)d_in[8];
    const float* gn_g1      = (const float*)d_in[9];
    const float* gn_b1      = (const float*)d_in[10];
    const float* level_emb  = (const float*)d_in[11];
    const float* so_W       = (const float*)d_in[12];
    const float* so_b       = (const float*)d_in[13];
    const float* aw_W       = (const float*)d_in[14];
    const float* aw_b       = (const float*)d_in[15];
    const float* vp_W       = (const float*)d_in[16];
    const float* vp_b       = (const float*)d_in[17];
    const float* op_W       = (const float*)d_in[18];
    const float* op_b       = (const float*)d_in[19];
    const float* ln1_g      = (const float*)d_in[20];
    const float* ln1_b      = (const float*)d_in[21];
    const float* l1_W       = (const float*)d_in[22];
    const float* l1_b       = (const float*)d_in[23];
    const float* l2_W       = (const float*)d_in[24];
    const float* l2_b       = (const float*)d_in[25];
    const float* ln2_g      = (const float*)d_in[26];
    const float* ln2_b      = (const float*)d_in[27];

    float *p_src, *p_offaw, *p_v, *p_attn, *p_ffn, *p_wcomb, *p_bcomb;
    cudaGetSymbolAddress((void**)&p_src,   g_src);
    cudaGetSymbolAddress((void**)&p_offaw, g_offaw);
    cudaGetSymbolAddress((void**)&p_v,     g_v);
    cudaGetSymbolAddress((void**)&p_attn,  g_attn);
    cudaGetSymbolAddress((void**)&p_ffn,   g_ffn);
    cudaGetSymbolAddress((void**)&p_wcomb, g_wcomb);
    cudaGetSymbolAddress((void**)&p_bcomb, g_bcomb);

    // pos embed + ref points + weight packing
    k_pos<<<(LTc * DD + 255) / 256, 256>>>(level_emb);
    k_pack<<<(NLAY * DD * DD + 255) / 256, 256>>>(so_W, so_b, aw_W, aw_b);

    // projections (tensor cores), token-major into g_src
    for (int b = 0; b < NB; b++) {
        k_proj_tf32<<<dim3(DD / 64, N0c / 128), 256>>>(
            feat0 + (size_t)b * DD * N0c, proj_w0, proj_b0,
            p_src + (size_t)(b * LTc) * DD, N0c);
        k_proj_tf32<<<dim3(DD / 64, N1c / 128), 256>>>(
            feat1 + (size_t)b * DD * N1c, proj_w1, proj_b1,
            p_src + (size_t)(b * LTc + N0c) * DD, N1c);
    }
    k_gn_stats<<<NB * 32, 256>>>(0, N0c);
    k_gn_apply<<<(NB * N0c * DD + 255) / 256, 256>>>(0, N0c, gn_g0, gn_b0);
    k_gn_stats<<<NB * 32, 256>>>(N0c, N1c);
    k_gn_apply<<<(NB * N1c * DD + 255) / 256, 256>>>(N0c, N1c, gn_g1, gn_b1);

    // encoder layers
    for (int i = 0; i < NLAY; i++) {
        // combined offsets+aw logits, with fused q = src + pos
        k_gemm_tf32<false, true><<<dim3(3, MT / 128), 256>>>(
            p_src, p_wcomb + (size_t)i * DD * DD, p_bcomb + (size_t)i * DD,
            p_offaw, DD, DD);
        // value projection
        k_gemm_tf32<false, false><<<dim3(3, MT / 128), 256>>>(
            p_src, vp_W + (size_t)i * DD * DD, vp_b + (size_t)i * DD, p_v, DD, DD);
        // deformable attention (softmax fused)
        k_deform<<<NB * LTc, 256>>>();
        // output projection + residual + LN1 (fused)
        k_gemm_ln<<<MT / 128, 256>>>(
            p_attn, op_W + (size_t)i * DD * DD, op_b + (size_t)i * DD,
            ln1_g + (size_t)i * DD, ln1_b + (size_t)i * DD, p_src, DD);
        // FFN up + ReLU
        k_gemm_tf32<true, false><<<dim3(4, MT / 128), 256>>>(
            p_src, l1_W + (size_t)i * DD * FFc, l1_b + (size_t)i * FFc, p_ffn, FFc, DD);
        // FFN down + residual + LN2 (fused)
        k_gemm_ln<<<MT / 128, 256>>>(
            p_ffn, l2_W + (size_t)i * FFc * DD, l2_b + (size_t)i * DD,
            ln2_g + (size_t)i * DD, ln2_b + (size_t)i * DD, p_src, FFc);
    }

    // outputs: m0 then m1, each (B, D, H, W)
    float* out = (float*)d_out;
    k_out<<<dim3(N0c / 32, DD / 32, NB), dim3(32, 32)>>>(out, 0, N0c);
    k_out<<<dim3(N1c / 32, DD / 32, NB), dim3(32, 32)>>>(out + (size_t)NB * DD * N0c, N0c, N1c);
}

// round 8
// speedup vs baseline: 1.5792x; 1.1068x over previous
#include <cuda_runtime.h>
#include <math.h>
#include <stdint.h>

// ---------------- problem constants ----------------
#define NB   2
#define DD   192
#define NHH  8
#define HDD  24
#define H0c  96
#define W0c  96
#define H1c  48
#define W1c  48
#define N0c  (H0c*W0c)      // 9216
#define N1c  (H1c*W1c)      // 2304
#define LTc  (N0c+N1c)      // 11520
#define MT   (NB*LTc)       // 23040
#define FFc  256
#define NLAY 6

// ---------------- device scratch ----------------
__device__ float g_src  [MT*DD];      // running activation (fp32 exact trunk)
__device__ float g_srnd [MT*DD];      // rna(src)  — GEMM A input
__device__ float g_qrnd [MT*DD];      // rna(src+pos) — GEMM A input
__device__ float g_pos  [LTc*DD];
__device__ float g_ref  [LTc*2];
__device__ float g_offaw[MT*DD];      // offsets(128) + aw logits(64)
__device__ float g_v    [MT*DD];
__device__ float g_attn [MT*DD];      // rna-rounded
__device__ float g_ffn  [MT*FFc];     // rna-rounded
__device__ float g_wcomb[NLAY*DD*DD]; // rna(so_W || aw_W)
__device__ float g_bcomb[NLAY*DD];
__device__ float g_wv   [NLAY*DD*DD];
__device__ float g_wo   [NLAY*DD*DD];
__device__ float g_w1   [NLAY*DD*FFc];
__device__ float g_w2   [NLAY*FFc*DD];
__device__ float g_gnm  [NB*32];
__device__ float g_gnr  [NB*32];

// ---------------- helpers ----------------
__device__ __forceinline__ uint32_t f2tf32(float x) {
    uint32_t r;
    asm("cvt.rna.tf32.f32 %0, %1;" : "=r"(r) : "f"(x));
    return r;
}
__device__ __forceinline__ float rnd(float x) { return __uint_as_float(f2tf32(x)); }

__device__ __forceinline__ void mma_tf32(float* c, const uint32_t* a, const uint32_t* b) {
    asm volatile(
        "mma.sync.aligned.m16n8k8.row.col.f32.tf32.tf32.f32 "
        "{%0,%1,%2,%3}, {%4,%5,%6,%7}, {%8,%9}, {%0,%1,%2,%3};"
        : "+f"(c[0]), "+f"(c[1]), "+f"(c[2]), "+f"(c[3])
        : "r"(a[0]), "r"(a[1]), "r"(a[2]), "r"(a[3]), "r"(b[0]), "r"(b[1]));
}
__device__ __forceinline__ uint32_t s2u(const void* p) {
    return (uint32_t)__cvta_generic_to_shared(p);
}
__device__ __forceinline__ void cp16(uint32_t dst, const void* src) {
    asm volatile("cp.async.cg.shared.global [%0], [%1], 16;" :: "r"(dst), "l"(src));
}
__device__ __forceinline__ void cp_commit() { asm volatile("cp.async.commit_group;"); }
template<int W> __device__ __forceinline__ void cp_wait() {
    asm volatile("cp.async.wait_group %0;" :: "n"(W));
}

// ---------------- pos embed + reference points ----------------
__global__ void k_pos(const float* __restrict__ level_embed) {
    int idx = blockIdx.x * blockDim.x + threadIdx.x;
    if (idx >= LTc * DD) return;
    int l = idx / DD, d = idx % DD;
    int lev, i, j, Hc, Wc;
    if (l < N0c) { lev = 0; i = l / W0c; j = l % W0c; Hc = H0c; Wc = W0c; }
    else         { lev = 1; int ll = l - N0c; i = ll / W1c; j = ll % W1c; Hc = H1c; Wc = W1c; }
    const float TWO_PI = 6.283185307179586f;
    float v; int dd;
    if (d < 96) { v = ((float)i + 0.5f) / ((float)Hc + 1e-6f) * TWO_PI; dd = d; }
    else        { v = ((float)j + 0.5f) / ((float)Wc + 1e-6f) * TWO_PI; dd = d - 96; }
    float e = (float)(2 * (dd >> 1)) / 96.0f;
    float t = v / powf(10000.0f, e);
    float val = (dd & 1) ? cosf(t) : sinf(t);
    g_pos[idx] = val + level_embed[lev * DD + d];
    if (d == 0) {
        g_ref[l * 2 + 0] = ((float)j + 0.5f) / (float)Wc;
        g_ref[l * 2 + 1] = ((float)i + 0.5f) / (float)Hc;
    }
}

// ---------------- pack so_W||aw_W into one [D,192] weight (rna-rounded) ------
__global__ void k_pack(const float* __restrict__ soW, const float* __restrict__ sob,
                       const float* __restrict__ awW, const float* __restrict__ awb) {
    int idx = blockIdx.x * blockDim.x + threadIdx.x;
    if (idx < NLAY * DD * DD) {
        int i = idx / (DD * DD);
        int rem = idx % (DD * DD);
        int k = rem / DD, n = rem % DD;
        float w = (n < 128) ? soW[(size_t)i * DD * 128 + k * 128 + n]
                            : awW[(size_t)i * DD * 64 + k * 64 + (n - 128)];
        g_wcomb[idx] = rnd(w);
    }
    if (idx < NLAY * DD) {
        int i = idx / DD, n = idx % DD;
        g_bcomb[idx] = (n < 128) ? sob[i * 128 + n] : awb[i * 64 + (n - 128)];
    }
}

// ---------------- generic rna-round copy ----------------
__global__ void k_round(const float* __restrict__ in, float* __restrict__ out, int n) {
    int idx = blockIdx.x * blockDim.x + threadIdx.x;
    if (idx < n) out[idx] = rnd(in[idx]);
}

// ---------------- main TF32 GEMM: C = A@W + bias, 3-stage cp.async ----------
// A, W pre-rounded to tf32 grid. BM=128, BN=64, BK=16, 256 thr,
// 8 warps (4m x 2n), warp tile 32x32. K multiple of 16 (>=32), N mult of 64.
template <bool RELU, bool ROUND>
__global__ __launch_bounds__(256) void k_gemm_main(
    const float* __restrict__ A, const float* __restrict__ Bm,
    const float* __restrict__ bias, float* __restrict__ C,
    int N, int K)
{
    __shared__ float As[3][128][20];   // [m][k], stride 20 -> conflict-free frags
    __shared__ float Bs[3][16][72];    // [k][n], stride 72 -> bank = 8k+n
    const int bm = blockIdx.y * 128, bn = blockIdx.x * 64;
    const int tid = threadIdx.x;
    const int warp = tid >> 5, lane = tid & 31;
    const int wm = (warp >> 1) * 32, wn = (warp & 1) * 32;
    const int g = lane >> 2, tig = lane & 3;
    const float* Ag = A + (size_t)bm * K;

    float acc[2][4][4];
    #pragma unroll
    for (int t = 0; t < 2; t++)
        #pragma unroll
        for (int u = 0; u < 4; u++)
            #pragma unroll
            for (int r = 0; r < 4; r++) acc[t][u][r] = 0.f;

    const int lm = tid >> 2, lk4 = (tid & 3) * 4;
    const int lbk = tid >> 4, lbn4 = (tid & 15) * 4;

    auto load_stage = [&](int st, int kk) {
        cp16(s2u(&As[st][lm][lk4]),      Ag + (size_t)lm * K + kk + lk4);
        cp16(s2u(&As[st][lm + 64][lk4]), Ag + (size_t)(lm + 64) * K + kk + lk4);
        cp16(s2u(&Bs[st][lbk][lbn4]),    Bm + (size_t)(kk + lbk) * N + bn + lbn4);
    };

    const int niter = K / 16;
    load_stage(0, 0);  cp_commit();
    load_stage(1, 16); cp_commit();
    cp_wait<1>();
    __syncthreads();

    for (int it = 0; it < niter; it++) {
        if (it + 2 < niter) load_stage((it + 2) % 3, (it + 2) * 16);
        cp_commit();
        const int buf = it % 3;
        #pragma unroll
        for (int s = 0; s < 16; s += 8) {
            uint32_t af[2][4], bf[4][2];
            #pragma unroll
            for (int t = 0; t < 2; t++) {
                af[t][0] = __float_as_uint(As[buf][wm + t * 16 + g    ][s + tig]);
                af[t][1] = __float_as_uint(As[buf][wm + t * 16 + g + 8][s + tig]);
                af[t][2] = __float_as_uint(As[buf][wm + t * 16 + g    ][s + tig + 4]);
                af[t][3] = __float_as_uint(As[buf][wm + t * 16 + g + 8][s + tig + 4]);
            }
            #pragma unroll
            for (int u = 0; u < 4; u++) {
                bf[u][0] = __float_as_uint(Bs[buf][s + tig    ][wn + u * 8 + g]);
                bf[u][1] = __float_as_uint(Bs[buf][s + tig + 4][wn + u * 8 + g]);
            }
            #pragma unroll
            for (int t = 0; t < 2; t++)
                #pragma unroll
                for (int u = 0; u < 4; u++)
                    mma_tf32(acc[t][u], af[t], bf[u]);
        }
        cp_wait<1>();
        __syncthreads();
    }

    #pragma unroll
    for (int t = 0; t < 2; t++) {
        int row0 = bm + wm + t * 16 + g;
        int row1 = row0 + 8;
        #pragma unroll
        for (int u = 0; u < 4; u++) {
            int col = bn + wn + u * 8 + tig * 2;
            float b0 = bias[col], b1 = bias[col + 1];
            float2 v0 = make_float2(acc[t][u][0] + b0, acc[t][u][1] + b1);
            float2 v1 = make_float2(acc[t][u][2] + b0, acc[t][u][3] + b1);
            if (RELU) {
                v0.x = fmaxf(v0.x, 0.f); v0.y = fmaxf(v0.y, 0.f);
                v1.x = fmaxf(v1.x, 0.f); v1.y = fmaxf(v1.y, 0.f);
            }
            if (ROUND) {
                v0.x = rnd(v0.x); v0.y = rnd(v0.y);
                v1.x = rnd(v1.x); v1.y = rnd(v1.y);
            }
            *reinterpret_cast<float2*>(&C[(size_t)row0 * N + col]) = v0;
            *reinterpret_cast<float2*>(&C[(size_t)row1 * N + col]) = v1;
        }
    }
}

// ---------------- TF32 GEMM + residual + LayerNorm, 2-stage cp.async --------
// out_row = LN(res_row + A@W + bias)*gamma + beta -> g_src (+ rounded copies)
// BM=64, BN=192, BK=16, 256 thr, 8 warps (2m x 4n), warp tile 32x48.
template <bool WRITEQ>
__global__ __launch_bounds__(256) void k_gemm_ln(
    const float* __restrict__ A, const float* __restrict__ Bm,
    const float* __restrict__ bias,
    const float* __restrict__ gamma, const float* __restrict__ beta,
    int K)
{
    __shared__ __align__(16) char sbuf[10240 + 25600];
    float (*As)[64][20]  = reinterpret_cast<float(*)[64][20]>(sbuf);
    float (*Bs)[16][200] = reinterpret_cast<float(*)[16][200]>(sbuf + 10240);

    const int bm = blockIdx.x * 64;
    const int tid = threadIdx.x;
    const int warp = tid >> 5, lane = tid & 31;
    const int wm = (warp >> 2) * 32, wn = (warp & 3) * 48;
    const int g = lane >> 2, tig = lane & 3;
    const float* Ag = A + (size_t)bm * K;

    float acc[2][6][4];
    #pragma unroll
    for (int t = 0; t < 2; t++)
        #pragma unroll
        for (int u = 0; u < 6; u++)
            #pragma unroll
            for (int r = 0; r < 4; r++) acc[t][u][r] = 0.f;

    const int lm = tid >> 2, lk4 = (tid & 3) * 4;

    auto load_stage = [&](int st, int kk) {
        cp16(s2u(&As[st][lm][lk4]), Ag + (size_t)lm * K + kk + lk4);
        #pragma unroll
        for (int j = 0; j < 3; j++) {
            int idx = tid + j * 256;
            int k = idx / 48, n4 = (idx % 48) * 4;
            cp16(s2u(&Bs[st][k][n4]), Bm + (size_t)(kk + k) * DD + n4);
        }
    };

    const int niter = K / 16;
    load_stage(0, 0); cp_commit();
    cp_wait<0>();
    __syncthreads();

    for (int it = 0; it < niter; it++) {
        if (it + 1 < niter) load_stage((it + 1) & 1, (it + 1) * 16);
        cp_commit();
        const int buf = it & 1;
        #pragma unroll
        for (int s = 0; s < 16; s += 8) {
            uint32_t af[2][4], bf[6][2];
            #pragma unroll
            for (int t = 0; t < 2; t++) {
                af[t][0] = __float_as_uint(As[buf][wm + t * 16 + g    ][s + tig]);
                af[t][1] = __float_as_uint(As[buf][wm + t * 16 + g + 8][s + tig]);
                af[t][2] = __float_as_uint(As[buf][wm + t * 16 + g    ][s + tig + 4]);
                af[t][3] = __float_as_uint(As[buf][wm + t * 16 + g + 8][s + tig + 4]);
            }
            #pragma unroll
            for (int u = 0; u < 6; u++) {
                bf[u][0] = __float_as_uint(Bs[buf][s + tig    ][wn + u * 8 + g]);
                bf[u][1] = __float_as_uint(Bs[buf][s + tig + 4][wn + u * 8 + g]);
            }
            #pragma unroll
            for (int t = 0; t < 2; t++)
                #pragma unroll
                for (int u = 0; u < 6; u++)
                    mma_tf32(acc[t][u], af[t], bf[u]);
        }
        cp_wait<0>();
        __syncthreads();
    }

    // ---- fused epilogue: x = acc + bias + res; LayerNorm per row ----
    float* psum  = reinterpret_cast<float*>(sbuf);   // [64][18]
    float* psum2 = psum + 64 * 18;                   // [64][18]
    float* smu   = psum2 + 64 * 18;                  // [64]
    float* srstd = smu + 64;                         // [64]
    const int widx = (warp & 3) * 4 + tig;

    #pragma unroll
    for (int t = 0; t < 2; t++) {
        #pragma unroll
        for (int half = 0; half < 2; half++) {
            int row = wm + t * 16 + g + half * 8;
            const float* rr = g_src + (size_t)(bm + row) * DD;
            float s = 0.f, s2 = 0.f;
            #pragma unroll
            for (int u = 0; u < 6; u++) {
                int col = wn + u * 8 + tig * 2;
                float2 rv = *reinterpret_cast<const float2*>(&rr[col]);
                float x0 = acc[t][u][half * 2 + 0] + bias[col]     + rv.x;
                float x1 = acc[t][u][half * 2 + 1] + bias[col + 1] + rv.y;
                acc[t][u][half * 2 + 0] = x0;
                acc[t][u][half * 2 + 1] = x1;
                s += x0 + x1;
                s2 += x0 * x0 + x1 * x1;
            }
            psum [row * 18 + widx] = s;
            psum2[row * 18 + widx] = s2;
        }
    }
    __syncthreads();
    if (tid < 64) {
        float s = 0.f, s2 = 0.f;
        #pragma unroll
        for (int j = 0; j < 16; j++) { s += psum[tid * 18 + j]; s2 += psum2[tid * 18 + j]; }
        float mu = s * (1.0f / 192.0f);
        float var = s2 * (1.0f / 192.0f) - mu * mu;
        smu[tid] = mu;
        srstd[tid] = rsqrtf(var + 1e-5f);
    }
    __syncthreads();
    #pragma unroll
    for (int t = 0; t < 2; t++) {
        #pragma unroll
        for (int half = 0; half < 2; half++) {
            int row = wm + t * 16 + g + half * 8;
            int rowg = bm + row;
            int posr = rowg >= LTc ? rowg - LTc : rowg;
            float mu = smu[row], rs = srstd[row];
            float* wr = g_src + (size_t)rowg * DD;
            float* ws = g_srnd + (size_t)rowg * DD;
            float* wq = g_qrnd + (size_t)rowg * DD;
            const float* pp = g_pos + (size_t)posr * DD;
            #pragma unroll
            for (int u = 0; u < 6; u++) {
                int col = wn + u * 8 + tig * 2;
                float o0 = (acc[t][u][half * 2 + 0] - mu) * rs * gamma[col]     + beta[col];
                float o1 = (acc[t][u][half * 2 + 1] - mu) * rs * gamma[col + 1] + beta[col + 1];
                *reinterpret_cast<float2*>(&wr[col]) = make_float2(o0, o1);
                *reinterpret_cast<float2*>(&ws[col]) = make_float2(rnd(o0), rnd(o1));
                if (WRITEQ) {
                    *reinterpret_cast<float2*>(&wq[col]) =
                        make_float2(rnd(o0 + pp[col]), rnd(o1 + pp[col + 1]));
                }
            }
        }
    }
}

// ---------------- projection GEMM (transposed operands), TF32 ---------------
// C[m,n] = sum_k A[k*M + m] * W[n*K + k] + bias[n]; C stride DD (token-major)
__global__ __launch_bounds__(256) void k_proj_tf32(
    const float* __restrict__ A, const float* __restrict__ Wt,
    const float* __restrict__ bias, float* __restrict__ C,
    int Mstride)
{
    __shared__ uint32_t As[2][16][132];
    __shared__ uint32_t Bs[2][16][68];
    const int bm = blockIdx.y * 128, bn = blockIdx.x * 64;
    const int tid = threadIdx.x;
    const int am = tid & 127, ak0 = tid >> 7;
    const int bk = tid & 15, bn0 = tid >> 4;
    const int warp = tid >> 5, lane = tid & 31;
    const int wm = (warp >> 1) * 32, wn = (warp & 1) * 32;
    const int g = lane >> 2, tig = lane & 3;
    const int K = DD;

    float acc[2][4][4];
    #pragma unroll
    for (int t = 0; t < 2; t++)
        #pragma unroll
        for (int u = 0; u < 4; u++)
            #pragma unroll
            for (int r = 0; r < 4; r++) acc[t][u][r] = 0.f;

    float ra[8], rb[4];
    #pragma unroll
    for (int r = 0; r < 8; r++) ra[r] = A[(size_t)(ak0 + 2 * r) * Mstride + bm + am];
    #pragma unroll
    for (int r = 0; r < 4; r++) rb[r] = Wt[(size_t)(bn + bn0 + 16 * r) * K + bk];
    #pragma unroll
    for (int r = 0; r < 8; r++) As[0][ak0 + 2 * r][am] = f2tf32(ra[r]);
    #pragma unroll
    for (int r = 0; r < 4; r++) Bs[0][bk][bn0 + 16 * r] = f2tf32(rb[r]);
    __syncthreads();

    const int niter = K / 16;
    int buf = 0;
    for (int it = 0; it < niter; it++) {
        const int k0 = (it + 1) * 16;
        const bool more = (it + 1 < niter);
        if (more) {
            #pragma unroll
            for (int r = 0; r < 8; r++) ra[r] = A[(size_t)(k0 + ak0 + 2 * r) * Mstride + bm + am];
            #pragma unroll
            for (int r = 0; r < 4; r++) rb[r] = Wt[(size_t)(bn + bn0 + 16 * r) * K + k0 + bk];
        }
        #pragma unroll
        for (int s = 0; s < 16; s += 8) {
            uint32_t af[2][4], bf[4][2];
            #pragma unroll
            for (int t = 0; t < 2; t++) {
                af[t][0] = As[buf][s + tig    ][wm + t * 16 + g];
                af[t][1] = As[buf][s + tig    ][wm + t * 16 + g + 8];
                af[t][2] = As[buf][s + tig + 4][wm + t * 16 + g];
                af[t][3] = As[buf][s + tig + 4][wm + t * 16 + g + 8];
            }
            #pragma unroll
            for (int u = 0; u < 4; u++) {
                bf[u][0] = Bs[buf][s + tig    ][wn + u * 8 + g];
                bf[u][1] = Bs[buf][s + tig + 4][wn + u * 8 + g];
            }
            #pragma unroll
            for (int t = 0; t < 2; t++)
                #pragma unroll
                for (int u = 0; u < 4; u++)
                    mma_tf32(acc[t][u], af[t], bf[u]);
        }
        if (more) {
            #pragma unroll
            for (int r = 0; r < 8; r++) As[buf ^ 1][ak0 + 2 * r][am] = f2tf32(ra[r]);
            #pragma unroll
            for (int r = 0; r < 4; r++) Bs[buf ^ 1][bk][bn0 + 16 * r] = f2tf32(rb[r]);
        }
        __syncthreads();
        buf ^= 1;
    }

    #pragma unroll
    for (int t = 0; t < 2; t++) {
        int row0 = bm + wm + t * 16 + g;
        int row1 = row0 + 8;
        #pragma unroll
        for (int u = 0; u < 4; u++) {
            int col = bn + wn + u * 8 + tig * 2;
            float b0 = bias[col], b1 = bias[col + 1];
            float2 v0 = make_float2(acc[t][u][0] + b0, acc[t][u][1] + b1);
            float2 v1 = make_float2(acc[t][u][2] + b0, acc[t][u][3] + b1);
            *reinterpret_cast<float2*>(&C[(size_t)row0 * DD + col]) = v0;
            *reinterpret_cast<float2*>(&C[(size_t)row1 * DD + col]) = v1;
        }
    }
}

// ---------------- GroupNorm: stats then apply (per level) ----------------
__global__ void k_gn_stats(int tokbase, int ntok) {
    int b = blockIdx.x >> 5, g = blockIdx.x & 31;
    const float* base = g_src + (size_t)(b * LTc + tokbase) * DD + g * 6;
    float s = 0.f, ss = 0.f;
    int tot = ntok * 6;
    for (int idx = threadIdx.x; idx < tot; idx += blockDim.x) {
        int hw = idx / 6, c = idx % 6;
        float x = base[(size_t)hw * DD + c];
        s += x; ss += x * x;
    }
    #pragma unroll
    for (int o = 16; o; o >>= 1) {
        s  += __shfl_xor_sync(0xffffffffu, s, o);
        ss += __shfl_xor_sync(0xffffffffu, ss, o);
    }
    __shared__ float sh[64];
    int w = threadIdx.x >> 5, lane = threadIdx.x & 31;
    if (lane == 0) { sh[w] = s; sh[w + 32] = ss; }
    __syncthreads();
    if (threadIdx.x == 0) {
        float S = 0.f, SS = 0.f;
        for (int w2 = 0; w2 < (int)(blockDim.x >> 5); w2++) { S += sh[w2]; SS += sh[w2 + 32]; }
        float inv = 1.0f / (float)tot;
        float mu = S * inv;
        float var = SS * inv - mu * mu;
        g_gnm[b * 32 + g] = mu;
        g_gnr[b * 32 + g] = rsqrtf(var + 1e-5f);
    }
}

// apply + produce rounded copies for layer-0 GEMM inputs
__global__ void k_gn_apply(int tokbase, int ntok,
                           const float* __restrict__ gg, const float* __restrict__ gb) {
    int idx = blockIdx.x * blockDim.x + threadIdx.x;
    int tot = NB * ntok * DD;
    if (idx >= tot) return;
    int c = idx % DD;
    int r = idx / DD;
    int hw = r % ntok;
    int b = r / ntok;
    size_t off = (size_t)(b * LTc + tokbase + hw) * DD + c;
    int g = c / 6;
    float x = g_src[off];
    float y = (x - g_gnm[b * 32 + g]) * g_gnr[b * 32 + g] * gg[c] + gb[c];
    g_src[off] = y;
    g_srnd[off] = rnd(y);
    g_qrnd[off] = rnd(y + g_pos[(size_t)(tokbase + hw) * DD + c]);
}

// ---------------- deformable attention gather (softmax fused) ----------------
__global__ __launch_bounds__(256) void k_deform() {
    int bq = blockIdx.x;
    int q = bq % LTc, b = bq / LTc;
    __shared__ float s_off[128];
    __shared__ float s_aw[64];
    int tid = threadIdx.x;
    size_t row = (size_t)(b * LTc + q);
    if (tid < 192) {
        float v = g_offaw[row * DD + tid];
        if (tid < 128) s_off[tid] = v;
        else           s_aw[tid - 128] = v;
    }
    float refx = g_ref[q * 2 + 0];
    float refy = g_ref[q * 2 + 1];
    __syncthreads();
    int h = tid >> 5, lane = tid & 31;

    float wv[8];
    float m = -1e30f;
    #pragma unroll
    for (int i = 0; i < 8; i++) { wv[i] = s_aw[h * 8 + i]; m = fmaxf(m, wv[i]); }
    float sum = 0.f;
    #pragma unroll
    for (int i = 0; i < 8; i++) { wv[i] = expf(wv[i] - m); sum += wv[i]; }
    float inv = 1.0f / sum;
    #pragma unroll
    for (int i = 0; i < 8; i++) wv[i] *= inv;

    float acc = 0.f;
    const float* vb = g_v + (size_t)b * LTc * DD + h * HDD + lane;
    #pragma unroll
    for (int l = 0; l < 2; l++) {
        const int Wl = l ? W1c : W0c;
        const int Hl = l ? H1c : H0c;
        const int st = l ? N0c : 0;
        const float fW = (float)Wl, fH = (float)Hl;
        #pragma unroll
        for (int p = 0; p < 4; p++) {
            float ox = s_off[h * 16 + l * 8 + p * 2 + 0];
            float oy = s_off[h * 16 + l * 8 + p * 2 + 1];
            float aww = wv[l * 4 + p];
            float x = (refx + ox / fW) * fW - 0.5f;
            float y = (refy + oy / fH) * fH - 0.5f;
            float x0 = floorf(x), y0 = floorf(y);
            float wx = x - x0, wy = y - y0;
            float cw[4] = { (1.f - wx) * (1.f - wy), wx * (1.f - wy),
                            (1.f - wx) * wy,         wx * wy };
            float cx[4] = { x0, x0 + 1.f, x0, x0 + 1.f };
            float cy[4] = { y0, y0, y0 + 1.f, y0 + 1.f };
            #pragma unroll
            for (int c4 = 0; c4 < 4; c4++) {
                bool valid = (cx[c4] >= 0.f) && (cx[c4] <= fW - 1.f) &&
                             (cy[c4] >= 0.f) && (cy[c4] <= fH - 1.f);
                if (valid && lane < HDD) {
                    int xi = (int)cx[c4], yi = (int)cy[c4];
                    acc = fmaf(cw[c4] * aww, vb[(size_t)(st + yi * Wl + xi) * DD], acc);
                }
            }
        }
    }
    // rounded: g_attn is a GEMM A-input
    if (lane < HDD) g_attn[row * DD + h * HDD + lane] = rnd(acc);
}

// ---------------- output transpose: (b, tok, d) -> (b, d, tok) per level ------
__global__ void k_out(float* __restrict__ dst, int tokbase, int ntok) {
    __shared__ float tile[32][33];
    int b = blockIdx.z;
    int tok0 = blockIdx.x * 32, d0 = blockIdx.y * 32;
    int tx = threadIdx.x, ty = threadIdx.y;
    tile[ty][tx] = g_src[(size_t)(b * LTc + tokbase + tok0 + ty) * DD + d0 + tx];
    __syncthreads();
    dst[(size_t)b * DD * ntok + (size_t)(d0 + ty) * ntok + tok0 + tx] = tile[tx][ty];
}

// ---------------- host orchestration ----------------
extern "C" void kernel_launch(void* const* d_in, const int* in_sizes, int n_in,
                              void* d_out, int out_size) {
    const float* feat0      = (const float*)d_in[0];
    const float* feat1      = (const float*)d_in[1];
    const float* proj_w0    = (const float*)d_in[3];
    const float* proj_b0    = (const float*)d_in[4];
    const float* gn_g0      = (const float*)d_in[5];
    const float* gn_b0      = (const float*)d_in[6];
    const float* proj_w1    = (const float*)d_in[7];
    const float* proj_b1    = (const float*)d_in[8];
    const float* gn_g1      = (const float*)d_in[9];
    const float* gn_b1      = (const float*)d_in[10];
    const float* level_emb  = (const float*)d_in[11];
    const float* so_W       = (const float*)d_in[12];
    const float* so_b       = (const float*)d_in[13];
    const float* aw_W       = (const float*)d_in[14];
    const float* aw_b       = (const float*)d_in[15];
    const float* vp_W       = (const float*)d_in[16];
    const float* vp_b       = (const float*)d_in[17];
    const float* op_W       = (const float*)d_in[18];
    const float* op_b       = (const float*)d_in[19];
    const float* ln1_g      = (const float*)d_in[20];
    const float* ln1_b      = (const float*)d_in[21];
    const float* l1_W       = (const float*)d_in[22];
    const float* l1_b       = (const float*)d_in[23];
    const float* l2_W       = (const float*)d_in[24];
    const float* l2_b       = (const float*)d_in[25];
    const float* ln2_g      = (const float*)d_in[26];
    const float* ln2_b      = (const float*)d_in[27];

    float *p_src, *p_qrnd, *p_srnd, *p_offaw, *p_v, *p_attn, *p_ffn;
    float *p_wcomb, *p_bcomb, *p_wv, *p_wo, *p_w1, *p_w2;
    cudaGetSymbolAddress((void**)&p_src,   g_src);
    cudaGetSymbolAddress((void**)&p_qrnd,  g_qrnd);
    cudaGetSymbolAddress((void**)&p_srnd,  g_srnd);
    cudaGetSymbolAddress((void**)&p_offaw, g_offaw);
    cudaGetSymbolAddress((void**)&p_v,     g_v);
    cudaGetSymbolAddress((void**)&p_attn,  g_attn);
    cudaGetSymbolAddress((void**)&p_ffn,   g_ffn);
    cudaGetSymbolAddress((void**)&p_wcomb, g_wcomb);
    cudaGetSymbolAddress((void**)&p_bcomb, g_bcomb);
    cudaGetSymbolAddress((void**)&p_wv,    g_wv);
    cudaGetSymbolAddress((void**)&p_wo,    g_wo);
    cudaGetSymbolAddress((void**)&p_w1,    g_w1);
    cudaGetSymbolAddress((void**)&p_w2,    g_w2);

    // pos/ref, weight packing + pre-rounding
    k_pos<<<(LTc * DD + 255) / 256, 256>>>(level_emb);
    k_pack<<<(NLAY * DD * DD + 255) / 256, 256>>>(so_W, so_b, aw_W, aw_b);
    k_round<<<(NLAY * DD * DD + 255) / 256, 256>>>(vp_W, p_wv, NLAY * DD * DD);
    k_round<<<(NLAY * DD * DD + 255) / 256, 256>>>(op_W, p_wo, NLAY * DD * DD);
    k_round<<<(NLAY * DD * FFc + 255) / 256, 256>>>(l1_W, p_w1, NLAY * DD * FFc);
    k_round<<<(NLAY * FFc * DD + 255) / 256, 256>>>(l2_W, p_w2, NLAY * FFc * DD);

    // projections -> g_src (token-major), then GN (+ rounded copies)
    for (int b = 0; b < NB; b++) {
        k_proj_tf32<<<dim3(DD / 64, N0c / 128), 256>>>(
            feat0 + (size_t)b * DD * N0c, proj_w0, proj_b0,
            p_src + (size_t)(b * LTc) * DD, N0c);
        k_proj_tf32<<<dim3(DD / 64, N1c / 128), 256>>>(
            feat1 + (size_t)b * DD * N1c, proj_w1, proj_b1,
            p_src + (size_t)(b * LTc + N0c) * DD, N1c);
    }
    k_gn_stats<<<NB * 32, 256>>>(0, N0c);
    k_gn_apply<<<(NB * N0c * DD + 255) / 256, 256>>>(0, N0c, gn_g0, gn_b0);
    k_gn_stats<<<NB * 32, 256>>>(N0c, N1c);
    k_gn_apply<<<(NB * N1c * DD + 255) / 256, 256>>>(N0c, N1c, gn_g1, gn_b1);

    // encoder layers
    for (int i = 0; i < NLAY; i++) {
        // offsets + aw logits from q = rna(src+pos)
        k_gemm_main<false, false><<<dim3(3, MT / 128), 256>>>(
            p_qrnd, p_wcomb + (size_t)i * DD * DD, p_bcomb + (size_t)i * DD,
            p_offaw, DD, DD);
        // value projection from rna(src)
        k_gemm_main<false, false><<<dim3(3, MT / 128), 256>>>(
            p_srnd, p_wv + (size_t)i * DD * DD, vp_b + (size_t)i * DD, p_v, DD, DD);
        // deformable attention (softmax fused, output rounded)
        k_deform<<<NB * LTc, 256>>>();
        // output projection + residual + LN1 (writes src + srnd)
        k_gemm_ln<false><<<MT / 64, 256>>>(
            p_attn, p_wo + (size_t)i * DD * DD, op_b + (size_t)i * DD,
            ln1_g + (size_t)i * DD, ln1_b + (size_t)i * DD, DD);
        // FFN up + ReLU (output rounded)
        k_gemm_main<true, true><<<dim3(4, MT / 128), 256>>>(
            p_srnd, p_w1 + (size_t)i * DD * FFc, l1_b + (size_t)i * FFc, p_ffn, FFc, DD);
        // FFN down + residual + LN2 (writes src + srnd + qrnd)
        k_gemm_ln<true><<<MT / 64, 256>>>(
            p_ffn, p_w2 + (size_t)i * FFc * DD, l2_b + (size_t)i * DD,
            ln2_g + (size_t)i * DD, ln2_b + (size_t)i * DD, FFc);
    }

    // outputs: m0 then m1, each (B, D, H, W)
    float* out = (float*)d_out;
    k_out<<<dim3(N0c / 32, DD / 32, NB), dim3(32, 32)>>>(out, 0, N0c);
    k_out<<<dim3(N1c / 32, DD / 32, NB), dim3(32, 32)>>>(out + (size_t)NB * DD * N0c, N0c, N1c);
}

// round 10
// speedup vs baseline: 1.7073x; 1.0811x over previous
#include <cuda_runtime.h>
#include <math.h>
#include <stdint.h>

// ---------------- problem constants ----------------
#define NB   2
#define DD   192
#define NHH  8
#define HDD  24
#define H0c  96
#define W0c  96
#define H1c  48
#define W1c  48
#define N0c  (H0c*W0c)      // 9216
#define N1c  (H1c*W1c)      // 2304
#define LTc  (N0c+N1c)      // 11520
#define MT   (NB*LTc)       // 23040
#define FFc  256
#define NLAY 6

#define LN_SMEM (15360 + 38400)   // dynamic smem for k_gemm_ln (3-stage)

// ---------------- device scratch ----------------
__device__ float g_src  [MT*DD];      // running activation (fp32 exact trunk)
__device__ float g_srnd [MT*DD];      // rna(src)  — GEMM A input
__device__ float g_qrnd [MT*DD];      // rna(src+pos) — GEMM A input
__device__ float g_pos  [LTc*DD];
__device__ float g_ref  [LTc*2];
__device__ float g_offaw[MT*DD];      // offsets(128) + aw logits(64)
__device__ float g_v    [MT*DD];
__device__ float g_attn [MT*DD];      // rna-rounded
__device__ float g_ffn  [MT*FFc];     // rna-rounded
__device__ float g_wcomb[NLAY*DD*DD]; // rna(so_W || aw_W)
__device__ float g_bcomb[NLAY*DD];
__device__ float g_wv   [NLAY*DD*DD];
__device__ float g_wo   [NLAY*DD*DD];
__device__ float g_w1   [NLAY*DD*FFc];
__device__ float g_w2   [NLAY*FFc*DD];
__device__ float g_gnm  [2*64];
__device__ float g_gnr  [2*64];

// ---------------- helpers ----------------
__device__ __forceinline__ uint32_t f2tf32(float x) {
    uint32_t r;
    asm("cvt.rna.tf32.f32 %0, %1;" : "=r"(r) : "f"(x));
    return r;
}
__device__ __forceinline__ float rnd(float x) { return __uint_as_float(f2tf32(x)); }

__device__ __forceinline__ void mma_tf32(float* c, const uint32_t* a, const uint32_t* b) {
    asm volatile(
        "mma.sync.aligned.m16n8k8.row.col.f32.tf32.tf32.f32 "
        "{%0,%1,%2,%3}, {%4,%5,%6,%7}, {%8,%9}, {%0,%1,%2,%3};"
        : "+f"(c[0]), "+f"(c[1]), "+f"(c[2]), "+f"(c[3])
        : "r"(a[0]), "r"(a[1]), "r"(a[2]), "r"(a[3]), "r"(b[0]), "r"(b[1]));
}
__device__ __forceinline__ uint32_t s2u(const void* p) {
    return (uint32_t)__cvta_generic_to_shared(p);
}
__device__ __forceinline__ void cp16(uint32_t dst, const void* src) {
    asm volatile("cp.async.cg.shared.global [%0], [%1], 16;" :: "r"(dst), "l"(src));
}
__device__ __forceinline__ void cp_commit() { asm volatile("cp.async.commit_group;"); }
template<int W> __device__ __forceinline__ void cp_wait() {
    asm volatile("cp.async.wait_group %0;" :: "n"(W));
}

// ---------------- fused weight prep (round + pack) — ONE launch --------------
__global__ void k_prep(const float* __restrict__ soW, const float* __restrict__ sob,
                       const float* __restrict__ awW, const float* __restrict__ awb,
                       const float* __restrict__ vpW, const float* __restrict__ opW,
                       const float* __restrict__ l1W, const float* __restrict__ l2W) {
    int idx = blockIdx.x * blockDim.x + threadIdx.x;
    const int SZ1 = NLAY * DD * DD;
    const int SZ2 = NLAY * DD * FFc;
    if (idx < SZ1) {
        int i = idx / (DD * DD);
        int rem = idx % (DD * DD);
        int k = rem / DD, n = rem % DD;
        float w = (n < 128) ? soW[(size_t)i * DD * 128 + k * 128 + n]
                            : awW[(size_t)i * DD * 64 + k * 64 + (n - 128)];
        g_wcomb[idx] = rnd(w);
        g_wv[idx] = rnd(vpW[idx]);
        g_wo[idx] = rnd(opW[idx]);
    }
    if (idx < SZ2) {
        g_w1[idx] = rnd(l1W[idx]);
        g_w2[idx] = rnd(l2W[idx]);
    }
    if (idx < NLAY * DD) {
        int i = idx / DD, n = idx % DD;
        g_bcomb[idx] = (n < 128) ? sob[i * 128 + n] : awb[i * 64 + (n - 128)];
    }
}

// ---------------- pos embed + reference points ----------------
__global__ void k_pos(const float* __restrict__ level_embed) {
    int idx = blockIdx.x * blockDim.x + threadIdx.x;
    if (idx >= LTc * DD) return;
    int l = idx / DD, d = idx % DD;
    int lev, i, j, Hc, Wc;
    if (l < N0c) { lev = 0; i = l / W0c; j = l % W0c; Hc = H0c; Wc = W0c; }
    else         { lev = 1; int ll = l - N0c; i = ll / W1c; j = ll % W1c; Hc = H1c; Wc = W1c; }
    const float TWO_PI = 6.283185307179586f;
    float v; int dd;
    if (d < 96) { v = ((float)i + 0.5f) / ((float)Hc + 1e-6f) * TWO_PI; dd = d; }
    else        { v = ((float)j + 0.5f) / ((float)Wc + 1e-6f) * TWO_PI; dd = d - 96; }
    float e = (float)(2 * (dd >> 1)) / 96.0f;
    float t = v / powf(10000.0f, e);
    float val = (dd & 1) ? cosf(t) : sinf(t);
    g_pos[idx] = val + level_embed[lev * DD + d];
    if (d == 0) {
        g_ref[l * 2 + 0] = ((float)j + 0.5f) / (float)Wc;
        g_ref[l * 2 + 1] = ((float)i + 0.5f) / (float)Hc;
    }
}

// ---------------- main TF32 GEMM: BM=64, BN=64, 128 thr, 3-stage cp.async ----
// A, W pre-rounded to tf32 grid. 4 warps (2m x 2n), warp tile 32x32.
template <bool RELU, bool ROUND>
__global__ __launch_bounds__(128) void k_gemm_main(
    const float* __restrict__ A, const float* __restrict__ Bm,
    const float* __restrict__ bias, float* __restrict__ C,
    int N, int K)
{
    __shared__ float As[3][64][20];    // [m][k], stride 20 -> conflict-free frags
    __shared__ float Bs[3][16][72];    // [k][n], stride 72 -> bank = 8k+n
    const int bm = blockIdx.y * 64, bn = blockIdx.x * 64;
    const int tid = threadIdx.x;
    const int warp = tid >> 5, lane = tid & 31;
    const int wm = (warp >> 1) * 32, wn = (warp & 1) * 32;
    const int g = lane >> 2, tig = lane & 3;
    const float* Ag = A + (size_t)bm * K;

    float acc[2][4][4];
    #pragma unroll
    for (int t = 0; t < 2; t++)
        #pragma unroll
        for (int u = 0; u < 4; u++)
            #pragma unroll
            for (int r = 0; r < 4; r++) acc[t][u][r] = 0.f;

    const int mA = tid >> 2, cA = (tid & 3) * 4;
    const int kB = tid >> 4, cB = (tid & 15) * 4;

    auto load_stage = [&](int st, int kk) {
        cp16(s2u(&As[st][mA][cA]),      Ag + (size_t)mA * K + kk + cA);
        cp16(s2u(&As[st][mA + 32][cA]), Ag + (size_t)(mA + 32) * K + kk + cA);
        cp16(s2u(&Bs[st][kB][cB]),      Bm + (size_t)(kk + kB) * N + bn + cB);
        cp16(s2u(&Bs[st][kB + 8][cB]),  Bm + (size_t)(kk + kB + 8) * N + bn + cB);
    };

    const int niter = K / 16;
    load_stage(0, 0);  cp_commit();
    load_stage(1, 16); cp_commit();
    cp_wait<1>();
    __syncthreads();

    for (int it = 0; it < niter; it++) {
        if (it + 2 < niter) load_stage((it + 2) % 3, (it + 2) * 16);
        cp_commit();
        const int buf = it % 3;
        #pragma unroll
        for (int s = 0; s < 16; s += 8) {
            uint32_t af[2][4], bf[4][2];
            #pragma unroll
            for (int t = 0; t < 2; t++) {
                af[t][0] = __float_as_uint(As[buf][wm + t * 16 + g    ][s + tig]);
                af[t][1] = __float_as_uint(As[buf][wm + t * 16 + g + 8][s + tig]);
                af[t][2] = __float_as_uint(As[buf][wm + t * 16 + g    ][s + tig + 4]);
                af[t][3] = __float_as_uint(As[buf][wm + t * 16 + g + 8][s + tig + 4]);
            }
            #pragma unroll
            for (int u = 0; u < 4; u++) {
                bf[u][0] = __float_as_uint(Bs[buf][s + tig    ][wn + u * 8 + g]);
                bf[u][1] = __float_as_uint(Bs[buf][s + tig + 4][wn + u * 8 + g]);
            }
            #pragma unroll
            for (int t = 0; t < 2; t++)
                #pragma unroll
                for (int u = 0; u < 4; u++)
                    mma_tf32(acc[t][u], af[t], bf[u]);
        }
        cp_wait<1>();
        __syncthreads();
    }

    #pragma unroll
    for (int t = 0; t < 2; t++) {
        int row0 = bm + wm + t * 16 + g;
        int row1 = row0 + 8;
        #pragma unroll
        for (int u = 0; u < 4; u++) {
            int col = bn + wn + u * 8 + tig * 2;
            float b0 = bias[col], b1 = bias[col + 1];
            float2 v0 = make_float2(acc[t][u][0] + b0, acc[t][u][1] + b1);
            float2 v1 = make_float2(acc[t][u][2] + b0, acc[t][u][3] + b1);
            if (RELU) {
                v0.x = fmaxf(v0.x, 0.f); v0.y = fmaxf(v0.y, 0.f);
                v1.x = fmaxf(v1.x, 0.f); v1.y = fmaxf(v1.y, 0.f);
            }
            if (ROUND) {
                v0.x = rnd(v0.x); v0.y = rnd(v0.y);
                v1.x = rnd(v1.x); v1.y = rnd(v1.y);
            }
            *reinterpret_cast<float2*>(&C[(size_t)row0 * N + col]) = v0;
            *reinterpret_cast<float2*>(&C[(size_t)row1 * N + col]) = v1;
        }
    }
}

// ---------------- TF32 GEMM + residual + LayerNorm, 3-stage cp.async --------
// out_row = LN(res_row + A@W + bias)*gamma + beta -> g_src (+ rounded copies)
// BM=64, BN=192, BK=16, 256 thr, 8 warps (2m x 4n), warp tile 32x48.
// Uses dynamic shared memory (LN_SMEM bytes) — exceeds 48KB static limit.
template <bool WRITEQ>
__global__ __launch_bounds__(256) void k_gemm_ln(
    const float* __restrict__ A, const float* __restrict__ Bm,
    const float* __restrict__ bias,
    const float* __restrict__ gamma, const float* __restrict__ beta,
    int K)
{
    extern __shared__ __align__(16) char sbuf[];
    float (*As)[64][20]  = reinterpret_cast<float(*)[64][20]>(sbuf);
    float (*Bs)[16][200] = reinterpret_cast<float(*)[16][200]>(sbuf + 15360);

    const int bm = blockIdx.x * 64;
    const int tid = threadIdx.x;
    const int warp = tid >> 5, lane = tid & 31;
    const int wm = (warp >> 2) * 32, wn = (warp & 3) * 48;
    const int g = lane >> 2, tig = lane & 3;
    const float* Ag = A + (size_t)bm * K;

    float acc[2][6][4];
    #pragma unroll
    for (int t = 0; t < 2; t++)
        #pragma unroll
        for (int u = 0; u < 6; u++)
            #pragma unroll
            for (int r = 0; r < 4; r++) acc[t][u][r] = 0.f;

    const int mA = tid >> 2, cA = (tid & 3) * 4;

    auto load_stage = [&](int st, int kk) {
        cp16(s2u(&As[st][mA][cA]), Ag + (size_t)mA * K + kk + cA);
        #pragma unroll
        for (int j = 0; j < 3; j++) {
            int idx = tid + j * 256;
            int k = idx / 48, n4 = (idx % 48) * 4;
            cp16(s2u(&Bs[st][k][n4]), Bm + (size_t)(kk + k) * DD + n4);
        }
    };

    const int niter = K / 16;
    load_stage(0, 0);  cp_commit();
    load_stage(1, 16); cp_commit();
    cp_wait<1>();
    __syncthreads();

    for (int it = 0; it < niter; it++) {
        if (it + 2 < niter) load_stage((it + 2) % 3, (it + 2) * 16);
        cp_commit();
        const int buf = it % 3;
        #pragma unroll
        for (int s = 0; s < 16; s += 8) {
            uint32_t af[2][4], bf[6][2];
            #pragma unroll
            for (int t = 0; t < 2; t++) {
                af[t][0] = __float_as_uint(As[buf][wm + t * 16 + g    ][s + tig]);
                af[t][1] = __float_as_uint(As[buf][wm + t * 16 + g + 8][s + tig]);
                af[t][2] = __float_as_uint(As[buf][wm + t * 16 + g    ][s + tig + 4]);
                af[t][3] = __float_as_uint(As[buf][wm + t * 16 + g + 8][s + tig + 4]);
            }
            #pragma unroll
            for (int u = 0; u < 6; u++) {
                bf[u][0] = __float_as_uint(Bs[buf][s + tig    ][wn + u * 8 + g]);
                bf[u][1] = __float_as_uint(Bs[buf][s + tig + 4][wn + u * 8 + g]);
            }
            #pragma unroll
            for (int t = 0; t < 2; t++)
                #pragma unroll
                for (int u = 0; u < 6; u++)
                    mma_tf32(acc[t][u], af[t], bf[u]);
        }
        cp_wait<1>();
        __syncthreads();
    }

    // ---- fused epilogue: x = acc + bias + res; LayerNorm per row ----
    float* psum  = reinterpret_cast<float*>(sbuf);   // [64][18]
    float* psum2 = psum + 64 * 18;                   // [64][18]
    float* smu   = psum2 + 64 * 18;                  // [64]
    float* srstd = smu + 64;                         // [64]
    const int widx = (warp & 3) * 4 + tig;

    #pragma unroll
    for (int t = 0; t < 2; t++) {
        #pragma unroll
        for (int half = 0; half < 2; half++) {
            int row = wm + t * 16 + g + half * 8;
            const float* rr = g_src + (size_t)(bm + row) * DD;
            float s = 0.f, s2 = 0.f;
            #pragma unroll
            for (int u = 0; u < 6; u++) {
                int col = wn + u * 8 + tig * 2;
                float2 rv = *reinterpret_cast<const float2*>(&rr[col]);
                float x0 = acc[t][u][half * 2 + 0] + bias[col]     + rv.x;
                float x1 = acc[t][u][half * 2 + 1] + bias[col + 1] + rv.y;
                acc[t][u][half * 2 + 0] = x0;
                acc[t][u][half * 2 + 1] = x1;
                s += x0 + x1;
                s2 += x0 * x0 + x1 * x1;
            }
            psum [row * 18 + widx] = s;
            psum2[row * 18 + widx] = s2;
        }
    }
    __syncthreads();
    if (tid < 64) {
        float s = 0.f, s2 = 0.f;
        #pragma unroll
        for (int j = 0; j < 16; j++) { s += psum[tid * 18 + j]; s2 += psum2[tid * 18 + j]; }
        float mu = s * (1.0f / 192.0f);
        float var = s2 * (1.0f / 192.0f) - mu * mu;
        smu[tid] = mu;
        srstd[tid] = rsqrtf(var + 1e-5f);
    }
    __syncthreads();
    #pragma unroll
    for (int t = 0; t < 2; t++) {
        #pragma unroll
        for (int half = 0; half < 2; half++) {
            int row = wm + t * 16 + g + half * 8;
            int rowg = bm + row;
            int posr = rowg >= LTc ? rowg - LTc : rowg;
            float mu = smu[row], rs = srstd[row];
            float* wr = g_src + (size_t)rowg * DD;
            float* ws = g_srnd + (size_t)rowg * DD;
            float* wq = g_qrnd + (size_t)rowg * DD;
            const float* pp = g_pos + (size_t)posr * DD;
            #pragma unroll
            for (int u = 0; u < 6; u++) {
                int col = wn + u * 8 + tig * 2;
                float o0 = (acc[t][u][half * 2 + 0] - mu) * rs * gamma[col]     + beta[col];
                float o1 = (acc[t][u][half * 2 + 1] - mu) * rs * gamma[col + 1] + beta[col + 1];
                *reinterpret_cast<float2*>(&wr[col]) = make_float2(o0, o1);
                *reinterpret_cast<float2*>(&ws[col]) = make_float2(rnd(o0), rnd(o1));
                if (WRITEQ) {
                    *reinterpret_cast<float2*>(&wq[col]) =
                        make_float2(rnd(o0 + pp[col]), rnd(o1 + pp[col + 1]));
                }
            }
        }
    }
}

// ---------------- merged projection GEMM (all 4 segments, one launch) -------
// C[m,n] = sum_k A[k*Mstr + m] * W[n*192 + k] + bias[n]; C token-major.
__global__ __launch_bounds__(256) void k_projall(
    const float* __restrict__ feat0, const float* __restrict__ feat1,
    const float* __restrict__ pw0, const float* __restrict__ pb0,
    const float* __restrict__ pw1, const float* __restrict__ pb1)
{
    const int by = blockIdx.y;
    const float* A; float* Cb; int Mstr, bm;
    const float* Wt; const float* bias;
    if (by < 72)       { A = feat0;                       Cb = g_src;                          Mstr = N0c; Wt = pw0; bias = pb0; bm = by * 128; }
    else if (by < 90)  { A = feat1;                       Cb = g_src + (size_t)N0c * DD;       Mstr = N1c; Wt = pw1; bias = pb1; bm = (by - 72) * 128; }
    else if (by < 162) { A = feat0 + (size_t)DD * N0c;    Cb = g_src + (size_t)LTc * DD;       Mstr = N0c; Wt = pw0; bias = pb0; bm = (by - 90) * 128; }
    else               { A = feat1 + (size_t)DD * N1c;    Cb = g_src + (size_t)(LTc + N0c) * DD; Mstr = N1c; Wt = pw1; bias = pb1; bm = (by - 162) * 128; }

    __shared__ uint32_t As[2][16][132];
    __shared__ uint32_t Bs[2][16][68];
    const int bn = blockIdx.x * 64;
    const int tid = threadIdx.x;
    const int am = tid & 127, ak0 = tid >> 7;
    const int bk = tid & 15, bn0 = tid >> 4;
    const int warp = tid >> 5, lane = tid & 31;
    const int wm = (warp >> 1) * 32, wn = (warp & 1) * 32;
    const int g = lane >> 2, tig = lane & 3;
    const int K = DD;

    float acc[2][4][4];
    #pragma unroll
    for (int t = 0; t < 2; t++)
        #pragma unroll
        for (int u = 0; u < 4; u++)
            #pragma unroll
            for (int r = 0; r < 4; r++) acc[t][u][r] = 0.f;

    float ra[8], rb[4];
    #pragma unroll
    for (int r = 0; r < 8; r++) ra[r] = A[(size_t)(ak0 + 2 * r) * Mstr + bm + am];
    #pragma unroll
    for (int r = 0; r < 4; r++) rb[r] = Wt[(size_t)(bn + bn0 + 16 * r) * K + bk];
    #pragma unroll
    for (int r = 0; r < 8; r++) As[0][ak0 + 2 * r][am] = f2tf32(ra[r]);
    #pragma unroll
    for (int r = 0; r < 4; r++) Bs[0][bk][bn0 + 16 * r] = f2tf32(rb[r]);
    __syncthreads();

    const int niter = K / 16;
    int buf = 0;
    for (int it = 0; it < niter; it++) {
        const int k0 = (it + 1) * 16;
        const bool more = (it + 1 < niter);
        if (more) {
            #pragma unroll
            for (int r = 0; r < 8; r++) ra[r] = A[(size_t)(k0 + ak0 + 2 * r) * Mstr + bm + am];
            #pragma unroll
            for (int r = 0; r < 4; r++) rb[r] = Wt[(size_t)(bn + bn0 + 16 * r) * K + k0 + bk];
        }
        #pragma unroll
        for (int s = 0; s < 16; s += 8) {
            uint32_t af[2][4], bf[4][2];
            #pragma unroll
            for (int t = 0; t < 2; t++) {
                af[t][0] = As[buf][s + tig    ][wm + t * 16 + g];
                af[t][1] = As[buf][s + tig    ][wm + t * 16 + g + 8];
                af[t][2] = As[buf][s + tig + 4][wm + t * 16 + g];
                af[t][3] = As[buf][s + tig + 4][wm + t * 16 + g + 8];
            }
            #pragma unroll
            for (int u = 0; u < 4; u++) {
                bf[u][0] = Bs[buf][s + tig    ][wn + u * 8 + g];
                bf[u][1] = Bs[buf][s + tig + 4][wn + u * 8 + g];
            }
            #pragma unroll
            for (int t = 0; t < 2; t++)
                #pragma unroll
                for (int u = 0; u < 4; u++)
                    mma_tf32(acc[t][u], af[t], bf[u]);
        }
        if (more) {
            #pragma unroll
            for (int r = 0; r < 8; r++) As[buf ^ 1][ak0 + 2 * r][am] = f2tf32(ra[r]);
            #pragma unroll
            for (int r = 0; r < 4; r++) Bs[buf ^ 1][bk][bn0 + 16 * r] = f2tf32(rb[r]);
        }
        __syncthreads();
        buf ^= 1;
    }

    #pragma unroll
    for (int t = 0; t < 2; t++) {
        int row0 = bm + wm + t * 16 + g;
        int row1 = row0 + 8;
        #pragma unroll
        for (int u = 0; u < 4; u++) {
            int col = bn + wn + u * 8 + tig * 2;
            float b0 = bias[col], b1 = bias[col + 1];
            float2 v0 = make_float2(acc[t][u][0] + b0, acc[t][u][1] + b1);
            float2 v1 = make_float2(acc[t][u][2] + b0, acc[t][u][3] + b1);
            *reinterpret_cast<float2*>(&Cb[(size_t)row0 * DD + col]) = v0;
            *reinterpret_cast<float2*>(&Cb[(size_t)row1 * DD + col]) = v1;
        }
    }
}

// ---------------- GroupNorm: stats (one launch, both levels) ----------------
__global__ void k_gn_stats() {
    int blk = blockIdx.x;
    int lev = blk >> 6, b = (blk >> 5) & 1, g = blk & 31;
    int tokbase = lev ? N0c : 0;
    int ntok = lev ? N1c : N0c;
    const float* base = g_src + (size_t)(b * LTc + tokbase) * DD + g * 6;
    float s = 0.f, ss = 0.f;
    int tot = ntok * 6;
    for (int idx = threadIdx.x; idx < tot; idx += blockDim.x) {
        int hw = idx / 6, c = idx % 6;
        float x = base[(size_t)hw * DD + c];
        s += x; ss += x * x;
    }
    #pragma unroll
    for (int o = 16; o; o >>= 1) {
        s  += __shfl_xor_sync(0xffffffffu, s, o);
        ss += __shfl_xor_sync(0xffffffffu, ss, o);
    }
    __shared__ float sh[64];
    int w = threadIdx.x >> 5, lane = threadIdx.x & 31;
    if (lane == 0) { sh[w] = s; sh[w + 32] = ss; }
    __syncthreads();
    if (threadIdx.x == 0) {
        float S = 0.f, SS = 0.f;
        for (int w2 = 0; w2 < (int)(blockDim.x >> 5); w2++) { S += sh[w2]; SS += sh[w2 + 32]; }
        float inv = 1.0f / (float)tot;
        float mu = S * inv;
        float var = SS * inv - mu * mu;
        g_gnm[lev * 64 + b * 32 + g] = mu;
        g_gnr[lev * 64 + b * 32 + g] = rsqrtf(var + 1e-5f);
    }
}

// apply (one launch) + rounded copies for layer-0 GEMM inputs
__global__ void k_gn_apply(const float* __restrict__ gg0, const float* __restrict__ gb0,
                           const float* __restrict__ gg1, const float* __restrict__ gb1) {
    int idx = blockIdx.x * blockDim.x + threadIdx.x;
    if (idx >= MT * DD) return;
    int c = idx % DD;
    int r = idx / DD;
    int b = r / LTc;
    int tok = r % LTc;
    int lev = tok >= N0c;
    const float* gg = lev ? gg1 : gg0;
    const float* gb = lev ? gb1 : gb0;
    int g = c / 6;
    float x = g_src[idx];
    float y = (x - g_gnm[lev * 64 + b * 32 + g]) * g_gnr[lev * 64 + b * 32 + g] * gg[c] + gb[c];
    g_src[idx] = y;
    g_srnd[idx] = rnd(y);
    g_qrnd[idx] = rnd(y + g_pos[(size_t)tok * DD + c]);
}

// ---------------- deformable attention gather (softmax fused) ----------------
__global__ __launch_bounds__(256) void k_deform() {
    int bq = blockIdx.x;
    int q = bq % LTc, b = bq / LTc;
    __shared__ float s_off[128];
    __shared__ float s_aw[64];
    int tid = threadIdx.x;
    size_t row = (size_t)(b * LTc + q);
    if (tid < 192) {
        float v = g_offaw[row * DD + tid];
        if (tid < 128) s_off[tid] = v;
        else           s_aw[tid - 128] = v;
    }
    float refx = g_ref[q * 2 + 0];
    float refy = g_ref[q * 2 + 1];
    __syncthreads();
    int h = tid >> 5, lane = tid & 31;

    float wv[8];
    float m = -1e30f;
    #pragma unroll
    for (int i = 0; i < 8; i++) { wv[i] = s_aw[h * 8 + i]; m = fmaxf(m, wv[i]); }
    float sum = 0.f;
    #pragma unroll
    for (int i = 0; i < 8; i++) { wv[i] = expf(wv[i] - m); sum += wv[i]; }
    float inv = 1.0f / sum;
    #pragma unroll
    for (int i = 0; i < 8; i++) wv[i] *= inv;

    float acc0 = 0.f, acc1 = 0.f;
    const float* vb = g_v + (size_t)b * LTc * DD + h * HDD + lane;
    #pragma unroll
    for (int l = 0; l < 2; l++) {
        const int Wl = l ? W1c : W0c;
        const int Hl = l ? H1c : H0c;
        const int st = l ? N0c : 0;
        const float fW = (float)Wl, fH = (float)Hl;
        #pragma unroll
        for (int p = 0; p < 4; p++) {
            float ox = s_off[h * 16 + l * 8 + p * 2 + 0];
            float oy = s_off[h * 16 + l * 8 + p * 2 + 1];
            float aww = wv[l * 4 + p];
            float x = (refx + ox / fW) * fW - 0.5f;
            float y = (refy + oy / fH) * fH - 0.5f;
            float x0 = floorf(x), y0 = floorf(y);
            float wx = x - x0, wy = y - y0;
            float cw[4] = { (1.f - wx) * (1.f - wy), wx * (1.f - wy),
                            (1.f - wx) * wy,         wx * wy };
            float cx[4] = { x0, x0 + 1.f, x0, x0 + 1.f };
            float cy[4] = { y0, y0, y0 + 1.f, y0 + 1.f };
            #pragma unroll
            for (int c4 = 0; c4 < 4; c4++) {
                bool valid = (cx[c4] >= 0.f) && (cx[c4] <= fW - 1.f) &&
                             (cy[c4] >= 0.f) && (cy[c4] <= fH - 1.f);
                if (valid && lane < HDD) {
                    int xi = (int)cx[c4], yi = (int)cy[c4];
                    float vload = vb[(size_t)(st + yi * Wl + xi) * DD];
                    if (c4 & 1) acc1 = fmaf(cw[c4] * aww, vload, acc1);
                    else        acc0 = fmaf(cw[c4] * aww, vload, acc0);
                }
            }
        }
    }
    if (lane < HDD) g_attn[row * DD + h * HDD + lane] = rnd(acc0 + acc1);
}

// ---------------- output transpose: (b, tok, d) -> (b, d, tok) per level ------
__global__ void k_out(float* __restrict__ dst, int tokbase, int ntok) {
    __shared__ float tile[32][33];
    int b = blockIdx.z;
    int tok0 = blockIdx.x * 32, d0 = blockIdx.y * 32;
    int tx = threadIdx.x, ty = threadIdx.y;
    tile[ty][tx] = g_src[(size_t)(b * LTc + tokbase + tok0 + ty) * DD + d0 + tx];
    __syncthreads();
    dst[(size_t)b * DD * ntok + (size_t)(d0 + ty) * ntok + tok0 + tx] = tile[tx][ty];
}

// ---------------- host orchestration ----------------
extern "C" void kernel_launch(void* const* d_in, const int* in_sizes, int n_in,
                              void* d_out, int out_size) {
    const float* feat0      = (const float*)d_in[0];
    const float* feat1      = (const float*)d_in[1];
    const float* proj_w0    = (const float*)d_in[3];
    const float* proj_b0    = (const float*)d_in[4];
    const float* gn_g0      = (const float*)d_in[5];
    const float* gn_b0      = (const float*)d_in[6];
    const float* proj_w1    = (const float*)d_in[7];
    const float* proj_b1    = (const float*)d_in[8];
    const float* gn_g1      = (const float*)d_in[9];
    const float* gn_b1      = (const float*)d_in[10];
    const float* level_emb  = (const float*)d_in[11];
    const float* so_W       = (const float*)d_in[12];
    const float* so_b       = (const float*)d_in[13];
    const float* aw_W       = (const float*)d_in[14];
    const float* aw_b       = (const float*)d_in[15];
    const float* vp_W       = (const float*)d_in[16];
    const float* vp_b       = (const float*)d_in[17];
    const float* op_W       = (const float*)d_in[18];
    const float* op_b       = (const float*)d_in[19];
    const float* ln1_g      = (const float*)d_in[20];
    const float* ln1_b      = (const float*)d_in[21];
    const float* l1_W       = (const float*)d_in[22];
    const float* l1_b       = (const float*)d_in[23];
    const float* l2_W       = (const float*)d_in[24];
    const float* l2_b       = (const float*)d_in[25];
    const float* ln2_g      = (const float*)d_in[26];
    const float* ln2_b      = (const float*)d_in[27];

    float *p_qrnd, *p_srnd, *p_offaw, *p_v, *p_attn, *p_ffn;
    float *p_wcomb, *p_bcomb, *p_wv, *p_wo, *p_w1, *p_w2;
    cudaGetSymbolAddress((void**)&p_qrnd,  g_qrnd);
    cudaGetSymbolAddress((void**)&p_srnd,  g_srnd);
    cudaGetSymbolAddress((void**)&p_offaw, g_offaw);
    cudaGetSymbolAddress((void**)&p_v,     g_v);
    cudaGetSymbolAddress((void**)&p_attn,  g_attn);
    cudaGetSymbolAddress((void**)&p_ffn,   g_ffn);
    cudaGetSymbolAddress((void**)&p_wcomb, g_wcomb);
    cudaGetSymbolAddress((void**)&p_bcomb, g_bcomb);
    cudaGetSymbolAddress((void**)&p_wv,    g_wv);
    cudaGetSymbolAddress((void**)&p_wo,    g_wo);
    cudaGetSymbolAddress((void**)&p_w1,    g_w1);
    cudaGetSymbolAddress((void**)&p_w2,    g_w2);

    // opt-in dynamic smem for the LN-fused GEMM (>48KB); attribute call is
    // host-side and allocation-free, safe under graph capture.
    static bool attr_done = false;
    if (!attr_done) {
        cudaFuncSetAttribute(k_gemm_ln<false>, cudaFuncAttributeMaxDynamicSharedMemorySize, LN_SMEM);
        cudaFuncSetAttribute(k_gemm_ln<true>,  cudaFuncAttributeMaxDynamicSharedMemorySize, LN_SMEM);
        attr_done = true;
    }

    // launches 1-5 (prelude) — launch #6 is the first k_gemm_main (for ncu -s 5)
    k_prep<<<(NLAY * DD * FFc + 255) / 256, 256>>>(so_W, so_b, aw_W, aw_b, vp_W, op_W, l1_W, l2_W);
    k_pos<<<(LTc * DD + 255) / 256, 256>>>(level_emb);
    k_projall<<<dim3(DD / 64, 180), 256>>>(feat0, feat1, proj_w0, proj_b0, proj_w1, proj_b1);
    k_gn_stats<<<128, 256>>>();
    k_gn_apply<<<(MT * DD + 255) / 256, 256>>>(gn_g0, gn_b0, gn_g1, gn_b1);

    // encoder layers
    for (int i = 0; i < NLAY; i++) {
        // offsets + aw logits from q = rna(src+pos)
        k_gemm_main<false, false><<<dim3(3, MT / 64), 128>>>(
            p_qrnd, p_wcomb + (size_t)i * DD * DD, p_bcomb + (size_t)i * DD,
            p_offaw, DD, DD);
        // value projection from rna(src)
        k_gemm_main<false, false><<<dim3(3, MT / 64), 128>>>(
            p_srnd, p_wv + (size_t)i * DD * DD, vp_b + (size_t)i * DD, p_v, DD, DD);
        // deformable attention (softmax fused, output rounded)
        k_deform<<<NB * LTc, 256>>>();
        // output projection + residual + LN1 (writes src + srnd)
        k_gemm_ln<false><<<MT / 64, 256, LN_SMEM>>>(
            p_attn, p_wo + (size_t)i * DD * DD, op_b + (size_t)i * DD,
            ln1_g + (size_t)i * DD, ln1_b + (size_t)i * DD, DD);
        // FFN up + ReLU (output rounded)
        k_gemm_main<true, true><<<dim3(4, MT / 64), 128>>>(
            p_srnd, p_w1 + (size_t)i * DD * FFc, l1_b + (size_t)i * FFc, p_ffn, FFc, DD);
        // FFN down + residual + LN2 (writes src + srnd + qrnd)
        k_gemm_ln<true><<<MT / 64, 256, LN_SMEM>>>(
            p_ffn, p_w2 + (size_t)i * FFc * DD, l2_b + (size_t)i * DD,
            ln2_g + (size_t)i * DD, ln2_b + (size_t)i * DD, FFc);
    }

    // outputs: m0 then m1, each (B, D, H, W)
    float* out = (float*)d_out;
    k_out<<<dim3(N0c / 32, DD / 32, NB), dim3(32, 32)>>>(out, 0, N0c);
    k_out<<<dim3(N1c / 32, DD / 32, NB), dim3(32, 32)>>>(out + (size_t)NB * DD * N0c, N0c, N1c);
}